// round 2
// baseline (speedup 1.0000x reference)
#include <cuda_runtime.h>
#include <math.h>

// ---------------------------------------------------------------------------
// Problem constants
// ---------------------------------------------------------------------------
#define B_   16
#define T_   1024
#define D_   512
#define H_   8
#define HD_  64
#define CO_  7
#define PRED_ 96
#define K_   8
#define LAT_ 2048
#define TP_  (T_ + PRED_)   // 1120
#define T1_  (T_ + 1)       // 1025

// ---------------------------------------------------------------------------
// Static device scratch (no runtime allocation allowed)
// ---------------------------------------------------------------------------
__device__ float g_res1[(size_t)B_ * T_ * D_];          // res - season[:, :T]
__device__ float g_v   [(size_t)B_ * T_ * D_];          // res1 @ in_proj_w
__device__ float g_gpre[(size_t)B_ * T1_ * D_];         // concat(v0, EMA states)
__device__ float g_res2[(size_t)B_ * T_ * D_];          // LN1 output
__device__ float g_hid [(size_t)B_ * T_ * LAT_];        // gelu(res2 @ ff_w1)
__device__ float g_pre [(size_t)B_ * T_ * D_];          // res2 + ffn (pre-LN2)
__device__ float g_gg  [(size_t)B_ * T_ * CO_];         // growth[:, :-1] @ gpred_w
__device__ float g_ss  [(size_t)B_ * T_ * CO_];         // season[:, :T] @ spred_w
__device__ float g_tk  [3 * K_ * B_ * D_];              // [param][k][b*D+d]: amp2, c1, phase

// ---------------------------------------------------------------------------
// Kernel 1: per-(b,d) 1024-pt radix-2 FFT + top-8 magnitude selection
// ---------------------------------------------------------------------------
__global__ __launch_bounds__(128) void fft_topk(const float* __restrict__ res) {
    __shared__ float re[1024], im[1024], mag[512];
    __shared__ float wbv[4];
    __shared__ int   wbi[4];
    int bd  = blockIdx.x;              // b*512 + d
    int tid = threadIdx.x;
    const float* x = res + (size_t)(bd >> 9) * T_ * D_ + (bd & 511);

    // load, bit-reversed (10 bits), imag = 0
    for (int t = tid; t < 1024; t += 128) {
        int r = __brev((unsigned)t) >> 22;
        re[r] = x[(size_t)t * D_];
        im[r] = 0.f;
    }
    __syncthreads();

    // iterative DIT, forward (e^{-i...}) matching numpy rfft
    for (int s = 1; s <= 10; s++) {
        int half = 1 << (s - 1);
        for (int j = tid; j < 512; j += 128) {
            int k  = j & (half - 1);
            int i0 = ((j >> (s - 1)) << s) + k;
            int i1 = i0 + half;
            float ang = -6.28318530717958647692f * ((float)k / (float)(half << 1));
            float wi_, wr_;
            sincosf(ang, &wi_, &wr_);
            float ar = re[i1], ai = im[i1];
            float tr = wr_ * ar - wi_ * ai;
            float ti = wr_ * ai + wi_ * ar;
            float br = re[i0], bi = im[i0];
            re[i0] = br + tr; im[i0] = bi + ti;
            re[i1] = br - tr; im[i1] = bi - ti;
        }
        __syncthreads();
    }

    // magnitudes^2 for bins 1..511 (bin 0 and Nyquist excluded by reference)
    for (int f = tid; f < 512; f += 128)
        mag[f] = (f == 0) ? -1.f : re[f] * re[f] + im[f] * im[f];
    __syncthreads();

    // top-8 via repeated block argmax
    for (int kk = 0; kk < K_; kk++) {
        float best = -2.f; int bidx = 0;
        for (int f = tid; f < 512; f += 128) {
            float m = mag[f];
            if (m > best) { best = m; bidx = f; }
        }
        #pragma unroll
        for (int o = 16; o; o >>= 1) {
            float ob = __shfl_down_sync(0xffffffffu, best, o);
            int   oi = __shfl_down_sync(0xffffffffu, bidx, o);
            if (ob > best) { best = ob; bidx = oi; }
        }
        if ((tid & 31) == 0) { wbv[tid >> 5] = best; wbi[tid >> 5] = bidx; }
        __syncthreads();
        if (tid == 0) {
            for (int w = 1; w < 4; w++)
                if (wbv[w] > best) { best = wbv[w]; bidx = wbi[w]; }
            float rr = re[bidx], ii = im[bidx];
            g_tk[(0 * K_ + kk) * (B_ * D_) + bd] = 2.f * sqrtf(best) * (1.f / 1024.f);
            g_tk[(1 * K_ + kk) * (B_ * D_) + bd] =
                6.28318530717958647692f * ((float)bidx * (1.f / 1024.f));
            g_tk[(2 * K_ + kk) * (B_ * D_) + bd] = atan2f(ii, rr);
            mag[bidx] = -1.f;
        }
        __syncthreads();
    }
}

// ---------------------------------------------------------------------------
// Kernel 2: season synthesis (all 1120 t) + fused res1 = res - season (t<1024)
// ---------------------------------------------------------------------------
__global__ __launch_bounds__(256) void season_k(const float* __restrict__ res,
                                                float* __restrict__ season_out) {
    __shared__ float sa[K_][256], sc[K_][256], sp[K_][256];
    int tid = threadIdx.x;
    int d   = blockIdx.x * 256 + tid;
    int b   = blockIdx.z;
    int bd  = b * D_ + d;
    #pragma unroll
    for (int k = 0; k < K_; k++) {
        sa[k][tid] = g_tk[(0 * K_ + k) * (B_ * D_) + bd];
        sc[k][tid] = g_tk[(1 * K_ + k) * (B_ * D_) + bd];
        sp[k][tid] = g_tk[(2 * K_ + k) * (B_ * D_) + bd];
    }
    __syncthreads();
    int t0 = blockIdx.y * 16;
    for (int tt = 0; tt < 16; tt++) {
        int t = t0 + tt;
        float tf = (float)t;
        float sum = 0.f;
        #pragma unroll
        for (int k = 0; k < K_; k++) {
            // replicate reference rounding: ((2pi*f) * t) + phase, no fma
            float a = __fadd_rn(__fmul_rn(sc[k][tid], tf), sp[k][tid]);
            sum += sa[k][tid] * cosf(a);
        }
        season_out[((size_t)b * TP_ + t) * D_ + d] = sum;
        if (t < T_) {
            size_t ro = ((size_t)b * T_ + t) * D_ + d;
            g_res1[ro] = res[ro] - sum;
        }
    }
}

// ---------------------------------------------------------------------------
// Kernel 3: generic fp32 SGEMM, 128x128x8 tile, 8x8 micro-tile
//   epi = 0: none, 1: exact gelu, 2: += ADD
// ---------------------------------------------------------------------------
__global__ __launch_bounds__(256) void sgemm_k(int M, int N, int K,
        const float* __restrict__ A, const float* __restrict__ Bm,
        float* __restrict__ C, int epi, const float* __restrict__ ADD) {
    __shared__ float As[8][128];
    __shared__ float Bs[8][128];
    int tid   = threadIdx.x;
    int gcol0 = blockIdx.x * 128;
    int grow0 = blockIdx.y * 128;
    int arow = tid >> 1,  acol = (tid & 1) * 4;
    int brow = tid >> 5,  bcol = (tid & 31) * 4;
    int ty   = tid >> 4,  tx   = tid & 15;
    float acc[8][8];
    #pragma unroll
    for (int i = 0; i < 8; i++)
        #pragma unroll
        for (int j = 0; j < 8; j++) acc[i][j] = 0.f;

    for (int k0 = 0; k0 < K; k0 += 8) {
        float4 av = make_float4(0.f, 0.f, 0.f, 0.f);
        int gr = grow0 + arow;
        if (gr < M) av = *(const float4*)(A + (size_t)gr * K + k0 + acol);
        As[acol + 0][arow] = av.x; As[acol + 1][arow] = av.y;
        As[acol + 2][arow] = av.z; As[acol + 3][arow] = av.w;
        *(float4*)&Bs[brow][bcol] =
            *(const float4*)(Bm + (size_t)(k0 + brow) * N + gcol0 + bcol);
        __syncthreads();
        #pragma unroll
        for (int kk = 0; kk < 8; kk++) {
            float ar[8], br[8];
            #pragma unroll
            for (int i = 0; i < 8; i++) ar[i] = As[kk][ty * 8 + i];
            #pragma unroll
            for (int j = 0; j < 8; j++) br[j] = Bs[kk][tx * 8 + j];
            #pragma unroll
            for (int i = 0; i < 8; i++)
                #pragma unroll
                for (int j = 0; j < 8; j++) acc[i][j] += ar[i] * br[j];
        }
        __syncthreads();
    }

    #pragma unroll
    for (int i = 0; i < 8; i++) {
        int r = grow0 + ty * 8 + i;
        if (r >= M) continue;
        #pragma unroll
        for (int j = 0; j < 8; j++) {
            int c = gcol0 + tx * 8 + j;
            float v = acc[i][j];
            if (epi == 1) v = 0.5f * v * (1.f + erff(v * 0.70710678118654752440f));
            else if (epi == 2) v += ADD[(size_t)r * N + c];
            C[(size_t)r * N + c] = v;
        }
    }
}

// ---------------------------------------------------------------------------
// Kernel 4: growth EMA scan (diff of projected values, per (b, h, hd))
// ---------------------------------------------------------------------------
__global__ __launch_bounds__(512) void growth_scan(const float* __restrict__ z0,
        const float* __restrict__ sw, const float* __restrict__ v0) {
    int b = blockIdx.x;
    int d = threadIdx.x;                       // 0..511, h = d>>6
    float w  = 1.f / (1.f + expf(-sw[d >> 6]));
    float om = 1.f - w;
    float prev  = z0[d];
    float state = v0[d];
    const float* vp = g_v    + (size_t)b * T_ * D_ + d;
    float*       gp = g_gpre + (size_t)b * T1_ * D_ + d;
    gp[0] = state;
    #pragma unroll 8
    for (int t = 0; t < T_; t++) {
        float cur = vp[(size_t)t * D_];
        state = w * state + om * (cur - prev);
        prev = cur;
        gp[(size_t)(t + 1) * D_] = state;
    }
}

// ---------------------------------------------------------------------------
// Kernel 5: LayerNorm over D=512. If G != null: x = A_row - growth[b, t+1]
// ---------------------------------------------------------------------------
__global__ __launch_bounds__(128) void ln_k(const float* __restrict__ A,
        const float* __restrict__ G, const float* __restrict__ gam,
        const float* __restrict__ bet, float* __restrict__ out) {
    __shared__ float sh[4], sh2[4];
    int row = blockIdx.x;
    int tid = threadIdx.x;
    const float* a = A + (size_t)row * D_;
    float x[4];
    if (G) {
        int b = row >> 10, t = row & 1023;
        const float* g = G + ((size_t)b * T1_ + t + 1) * D_;
        #pragma unroll
        for (int i = 0; i < 4; i++) x[i] = a[tid + i * 128] - g[tid + i * 128];
    } else {
        #pragma unroll
        for (int i = 0; i < 4; i++) x[i] = a[tid + i * 128];
    }
    float s = x[0] + x[1] + x[2] + x[3];
    #pragma unroll
    for (int o = 16; o; o >>= 1) s += __shfl_down_sync(0xffffffffu, s, o);
    if ((tid & 31) == 0) sh[tid >> 5] = s;
    __syncthreads();
    float mu = (sh[0] + sh[1] + sh[2] + sh[3]) * (1.f / 512.f);
    float vs = 0.f;
    #pragma unroll
    for (int i = 0; i < 4; i++) { float dx = x[i] - mu; vs += dx * dx; }
    #pragma unroll
    for (int o = 16; o; o >>= 1) vs += __shfl_down_sync(0xffffffffu, vs, o);
    if ((tid & 31) == 0) sh2[tid >> 5] = vs;
    __syncthreads();
    float var = (sh2[0] + sh2[1] + sh2[2] + sh2[3]) * (1.f / 512.f);
    float inv = rsqrtf(var + 1e-5f);
    float* o_ = out + (size_t)row * D_;
    #pragma unroll
    for (int i = 0; i < 4; i++) {
        int c = tid + i * 128;
        o_[c] = (x[i] - mu) * inv * gam[c] + bet[c];
    }
}

// ---------------------------------------------------------------------------
// Kernel 6: skinny [*,512] @ [512,7] (one block per (b,t) row; warp per col)
// ---------------------------------------------------------------------------
__global__ __launch_bounds__(256) void skinny7(const float* __restrict__ X,
        size_t bstride, const float* __restrict__ W, float* __restrict__ out) {
    __shared__ float xs[512];
    int r = blockIdx.x;
    int b = r >> 10, t = r & 1023;
    const float* x = X + (size_t)b * bstride + (size_t)t * D_;
    for (int i = threadIdx.x; i < 512; i += 256) xs[i] = x[i];
    __syncthreads();
    int w = threadIdx.x >> 5, lane = threadIdx.x & 31;
    if (w < CO_) {
        float s = 0.f;
        for (int i = lane; i < 512; i += 32) s += xs[i] * W[i * CO_ + w];
        #pragma unroll
        for (int o = 16; o; o >>= 1) s += __shfl_down_sync(0xffffffffu, s, o);
        if (!lane) out[(size_t)r * CO_ + w] = s;
    }
}

// ---------------------------------------------------------------------------
// Kernel 7: level EMA scan with aux growth term
// ---------------------------------------------------------------------------
__global__ __launch_bounds__(128) void level_scan(const float* __restrict__ level,
        const float* __restrict__ lsw, const float* __restrict__ lv0,
        float* __restrict__ out) {
    int idx = threadIdx.x;
    if (idx >= B_ * CO_) return;
    int b = idx / CO_, c = idx % CO_;
    float w  = 1.f / (1.f + expf(-lsw[c]));
    float om = 1.f - w;
    float state = lv0[c];
    const float* lp = level + (size_t)b * T_ * CO_ + c;
    const float* sp = g_ss  + (size_t)b * T_ * CO_ + c;
    const float* gp = g_gg  + (size_t)b * T_ * CO_ + c;
    float*       op = out   + (size_t)b * T_ * CO_ + c;
    #pragma unroll 4
    for (int t = 0; t < T_; t++) {
        float val = lp[t * CO_] - sp[t * CO_];
        state = w * state + om * val + w * gp[t * CO_];
        op[t * CO_] = state;
    }
}

// ---------------------------------------------------------------------------
// Launch
// ---------------------------------------------------------------------------
extern "C" void kernel_launch(void* const* d_in, const int* in_sizes, int n_in,
                              void* d_out, int out_size) {
    const float* res  = (const float*)d_in[0];
    const float* lvl  = (const float*)d_in[1];
    const float* inw  = (const float*)d_in[2];
    const float* outw = (const float*)d_in[3];
    const float* z0   = (const float*)d_in[4];
    const float* gsw  = (const float*)d_in[5];
    const float* gv0  = (const float*)d_in[6];
    const float* ffw1 = (const float*)d_in[7];
    const float* ffw2 = (const float*)d_in[8];
    const float* n1g  = (const float*)d_in[9];
    const float* n1b  = (const float*)d_in[10];
    const float* n2g  = (const float*)d_in[11];
    const float* n2b  = (const float*)d_in[12];
    const float* gpw  = (const float*)d_in[13];
    const float* spw  = (const float*)d_in[14];
    const float* lsw  = (const float*)d_in[15];
    const float* lv0  = (const float*)d_in[16];

    float* out        = (float*)d_out;
    float* out_res3   = out;                                    // [B, T, D]
    float* out_level  = out_res3  + (size_t)B_ * T_ * D_;       // [B, T, CO]
    float* out_growth = out_level + (size_t)B_ * T_ * CO_;      // [B, T+1, D]
    float* out_season = out_growth + (size_t)B_ * T1_ * D_;     // [B, T+PRED, D]

    float *p_res1, *p_v, *p_gpre, *p_res2, *p_hid, *p_pre, *p_gg, *p_ss;
    cudaGetSymbolAddress((void**)&p_res1, g_res1);
    cudaGetSymbolAddress((void**)&p_v,    g_v);
    cudaGetSymbolAddress((void**)&p_gpre, g_gpre);
    cudaGetSymbolAddress((void**)&p_res2, g_res2);
    cudaGetSymbolAddress((void**)&p_hid,  g_hid);
    cudaGetSymbolAddress((void**)&p_pre,  g_pre);
    cudaGetSymbolAddress((void**)&p_gg,   g_gg);
    cudaGetSymbolAddress((void**)&p_ss,   g_ss);

    // 1. FFT + top-k per (b,d)
    fft_topk<<<B_ * D_, 128>>>(res);
    // 2. season (all 1120 steps) + res1 for t<1024
    season_k<<<dim3(D_ / 256, TP_ / 16, B_), 256>>>(res, out_season);
    // 3. v = res1 @ in_proj_w
    sgemm_k<<<dim3(D_ / 128, (B_ * T_) / 128), 256>>>(
        B_ * T_, D_, D_, p_res1, inw, p_v, 0, nullptr);
    // 4. growth EMA scan (diffs, z0 prepend, v0 init)
    growth_scan<<<B_, 512>>>(z0, gsw, gv0);
    // 5. growth = gpre @ out_proj_w  -> output region
    sgemm_k<<<dim3(D_ / 128, (B_ * T1_ + 127) / 128), 256>>>(
        B_ * T1_, D_, D_, p_gpre, outw, out_growth, 0, nullptr);
    // 6. res2 = LN1(res1 - growth[:, 1:])
    ln_k<<<B_ * T_, 128>>>(p_res1, out_growth, n1g, n1b, p_res2);
    // 7. hidden = gelu(res2 @ ff_w1)
    sgemm_k<<<dim3(LAT_ / 128, (B_ * T_) / 128), 256>>>(
        B_ * T_, LAT_, D_, p_res2, ffw1, p_hid, 1, nullptr);
    // 8. pre = hidden @ ff_w2 + res2
    sgemm_k<<<dim3(D_ / 128, (B_ * T_) / 128), 256>>>(
        B_ * T_, D_, LAT_, p_hid, ffw2, p_pre, 2, p_res2);
    // 9. res3 = LN2(pre)  -> output region
    ln_k<<<B_ * T_, 128>>>(p_pre, nullptr, n2g, n2b, out_res3);
    // 10. g = growth[:, :-1] @ gpred_w ; s = season[:, :T] @ spred_w
    skinny7<<<B_ * T_, 256>>>(out_growth, (size_t)T1_ * D_, gpw, p_gg);
    skinny7<<<B_ * T_, 256>>>(out_season, (size_t)TP_ * D_, spw, p_ss);
    // 11. level EMA scan with aux growth -> output region
    level_scan<<<1, 128>>>(lvl, lsw, lv0, out_level);
}

// round 5
// speedup vs baseline: 2.1409x; 2.1409x over previous
#include <cuda_runtime.h>
#include <math.h>
#include <stdint.h>

// ---------------------------------------------------------------------------
// Problem constants
// ---------------------------------------------------------------------------
#define B_   16
#define T_   1024
#define D_   512
#define CO_  7
#define PRED_ 96
#define K_   8
#define LAT_ 2048
#define TP_  (T_ + PRED_)   // 1120
#define T1_  (T_ + 1)       // 1025
#define GSEG 16             // growth scan segments (64 steps each)
#define MPAD_G 16512        // 129*128 padded rows for growth GEMM

// ---------------------------------------------------------------------------
// Static device scratch
// ---------------------------------------------------------------------------
__device__ float g_res1[(size_t)B_ * T_ * D_];
__device__ float g_v   [(size_t)B_ * T_ * D_];
__device__ float g_gpre[(size_t)MPAD_G * D_];          // padded rows (pad stays 0)
__device__ float g_res2[(size_t)B_ * T_ * D_];
__device__ float g_hid [(size_t)B_ * T_ * LAT_];
__device__ float g_pre [(size_t)B_ * T_ * D_];
__device__ float g_gg  [(size_t)B_ * T_ * CO_];
__device__ float g_ss  [(size_t)B_ * T_ * CO_];
__device__ float g_tk  [3 * K_ * B_ * D_];
__device__ float g_segf[(size_t)B_ * GSEG * D_];       // growth segment finals
// transposed + tf32-rounded weights [N][K]
__device__ float g_wtin [(size_t)D_ * D_];
__device__ float g_wtout[(size_t)D_ * D_];
__device__ float g_wtf1 [(size_t)LAT_ * D_];
__device__ float g_wtf2 [(size_t)D_ * LAT_];

// ---------------------------------------------------------------------------
// Helpers
// ---------------------------------------------------------------------------
__device__ __forceinline__ uint32_t smem_u32(const void* p) {
    uint32_t a;
    asm("{ .reg .u64 t; cvta.to.shared.u64 t, %1; cvt.u32.u64 %0, t; }" : "=r"(a) : "l"(p));
    return a;
}
__device__ __forceinline__ float rnd_tf32(float x) {
    uint32_t o;
    asm("cvt.rna.tf32.f32 %0, %1;" : "=r"(o) : "f"(x));
    return __uint_as_float(o);
}
__device__ __forceinline__ void cp16(uint32_t dst, const void* src) {
    asm volatile("cp.async.cg.shared.global [%0], [%1], 16;" :: "r"(dst), "l"(src));
}
#define CP_COMMIT() asm volatile("cp.async.commit_group;" ::: "memory")

__device__ __forceinline__ void mma_tf32(float* c, const uint32_t* a, const uint32_t* b) {
    asm volatile(
        "mma.sync.aligned.m16n8k8.row.col.f32.tf32.tf32.f32 "
        "{%0,%1,%2,%3}, {%4,%5,%6,%7}, {%8,%9}, {%0,%1,%2,%3};"
        : "+f"(c[0]), "+f"(c[1]), "+f"(c[2]), "+f"(c[3])
        : "r"(a[0]), "r"(a[1]), "r"(a[2]), "r"(a[3]), "r"(b[0]), "r"(b[1]));
}

// ---------------------------------------------------------------------------
// Kernel: weight transpose [K,N] -> [N,K] with tf32 RN rounding
// ---------------------------------------------------------------------------
__global__ __launch_bounds__(256) void transpose_rnd(const float* __restrict__ W,
        float* __restrict__ WT, int K, int N) {
    __shared__ float t[32][33];
    int n0 = blockIdx.x * 32, k0 = blockIdx.y * 32;
    int tx = threadIdx.x & 31, ty = threadIdx.x >> 5;   // 32x8
    #pragma unroll
    for (int i = 0; i < 32; i += 8)
        t[ty + i][tx] = W[(size_t)(k0 + ty + i) * N + n0 + tx];
    __syncthreads();
    #pragma unroll
    for (int i = 0; i < 32; i += 8)
        WT[(size_t)(n0 + ty + i) * K + k0 + tx] = rnd_tf32(t[tx][ty + i]);
}

// ---------------------------------------------------------------------------
// Kernel 1: per-(b,d) 1024-pt radix-2 FFT + top-8 selection
// ---------------------------------------------------------------------------
__global__ __launch_bounds__(128) void fft_topk(const float* __restrict__ res) {
    __shared__ float re[1024], im[1024], mag[512];
    __shared__ float wbv[4];
    __shared__ int   wbi[4];
    int bd  = blockIdx.x;
    int tid = threadIdx.x;
    const float* x = res + (size_t)(bd >> 9) * T_ * D_ + (bd & 511);

    for (int t = tid; t < 1024; t += 128) {
        int r = __brev((unsigned)t) >> 22;
        re[r] = x[(size_t)t * D_];
        im[r] = 0.f;
    }
    __syncthreads();

    for (int s = 1; s <= 10; s++) {
        int half = 1 << (s - 1);
        for (int j = tid; j < 512; j += 128) {
            int k  = j & (half - 1);
            int i0 = ((j >> (s - 1)) << s) + k;
            int i1 = i0 + half;
            float ang = -6.28318530717958647692f * ((float)k / (float)(half << 1));
            float wi_, wr_;
            sincosf(ang, &wi_, &wr_);
            float ar = re[i1], ai = im[i1];
            float tr = wr_ * ar - wi_ * ai;
            float ti = wr_ * ai + wi_ * ar;
            float br = re[i0], bi = im[i0];
            re[i0] = br + tr; im[i0] = bi + ti;
            re[i1] = br - tr; im[i1] = bi - ti;
        }
        __syncthreads();
    }

    for (int f = tid; f < 512; f += 128)
        mag[f] = (f == 0) ? -1.f : re[f] * re[f] + im[f] * im[f];
    __syncthreads();

    for (int kk = 0; kk < K_; kk++) {
        float best = -2.f; int bidx = 0;
        for (int f = tid; f < 512; f += 128) {
            float m = mag[f];
            if (m > best) { best = m; bidx = f; }
        }
        #pragma unroll
        for (int o = 16; o; o >>= 1) {
            float ob = __shfl_down_sync(0xffffffffu, best, o);
            int   oi = __shfl_down_sync(0xffffffffu, bidx, o);
            if (ob > best) { best = ob; bidx = oi; }
        }
        if ((tid & 31) == 0) { wbv[tid >> 5] = best; wbi[tid >> 5] = bidx; }
        __syncthreads();
        if (tid == 0) {
            for (int w = 1; w < 4; w++)
                if (wbv[w] > best) { best = wbv[w]; bidx = wbi[w]; }
            float rr = re[bidx], ii = im[bidx];
            g_tk[(0 * K_ + kk) * (B_ * D_) + bd] = 2.f * sqrtf(best) * (1.f / 1024.f);
            g_tk[(1 * K_ + kk) * (B_ * D_) + bd] =
                6.28318530717958647692f * ((float)bidx * (1.f / 1024.f));
            g_tk[(2 * K_ + kk) * (B_ * D_) + bd] = atan2f(ii, rr);
            mag[bidx] = -1.f;
        }
        __syncthreads();
    }
}

// ---------------------------------------------------------------------------
// Kernel 2: season synthesis + res1 = res - season (rounded to tf32)
// ---------------------------------------------------------------------------
__global__ __launch_bounds__(256) void season_k(const float* __restrict__ res,
                                                float* __restrict__ season_out) {
    __shared__ float sa[K_][256], sc[K_][256], sp[K_][256];
    int tid = threadIdx.x;
    int d   = blockIdx.x * 256 + tid;
    int b   = blockIdx.z;
    int bd  = b * D_ + d;
    #pragma unroll
    for (int k = 0; k < K_; k++) {
        sa[k][tid] = g_tk[(0 * K_ + k) * (B_ * D_) + bd];
        sc[k][tid] = g_tk[(1 * K_ + k) * (B_ * D_) + bd];
        sp[k][tid] = g_tk[(2 * K_ + k) * (B_ * D_) + bd];
    }
    __syncthreads();
    int t0 = blockIdx.y * 16;
    for (int tt = 0; tt < 16; tt++) {
        int t = t0 + tt;
        float tf = (float)t;
        float sum = 0.f;
        #pragma unroll
        for (int k = 0; k < K_; k++) {
            float a = __fadd_rn(__fmul_rn(sc[k][tid], tf), sp[k][tid]);
            sum += sa[k][tid] * cosf(a);
        }
        season_out[((size_t)b * TP_ + t) * D_ + d] = sum;
        if (t < T_) {
            size_t ro = ((size_t)b * T_ + t) * D_ + d;
            g_res1[ro] = rnd_tf32(res[ro] - sum);
        }
    }
}

// ---------------------------------------------------------------------------
// Kernel 3: tf32 mma.sync GEMM.  C[M,N] = A[M,K] @ BT[N,K]^T
//   128x128x32 block tile, 8 warps x (64x32) warp tiles, cp.async dbl-buffer.
//   epi: 0 none, 1 gelu(+tf32 round), 2 +ADD
// ---------------------------------------------------------------------------
#define LDA_ 36
__global__ __launch_bounds__(256) void gemm_mma(int M, int N, int K,
        const float* __restrict__ A, const float* __restrict__ BT,
        float* __restrict__ C, int epi, const float* __restrict__ ADD) {
    extern __shared__ float smf[];
    float* As = smf;                       // [2][128][36]
    float* Bs = smf + 2 * 128 * LDA_;      // [2][128][36]
    uint32_t sa_u = smem_u32(As);
    uint32_t sb_u = smem_u32(Bs);

    int tid = threadIdx.x, wid = tid >> 5, lane = tid & 31;
    int wr = wid >> 2, wc = wid & 3;            // 2 x 4 warp grid
    int g = lane >> 2, tg = lane & 3;           // mma lane decomposition
    int row0 = blockIdx.y * 128, col0 = blockIdx.x * 128;

    float acc[4][4][4];
    #pragma unroll
    for (int i = 0; i < 4; i++)
        #pragma unroll
        for (int j = 0; j < 4; j++)
            #pragma unroll
            for (int q = 0; q < 4; q++) acc[i][j][q] = 0.f;

    const int S = K >> 5;
    int r_ld = tid >> 1;                        // 0..127 (2 threads per row)
    int q_ld = (tid & 1) * 4;                   // float4 quad index base

    // issue stage s into buffer buf
    #define ISSUE(s, buf) do {                                                  \
        int k0_ = (s) * 32;                                                     \
        uint32_t da_ = sa_u + (buf) * 128 * LDA_ * 4;                           \
        uint32_t db_ = sb_u + (buf) * 128 * LDA_ * 4;                           \
        _Pragma("unroll")                                                       \
        for (int p_ = 0; p_ < 4; p_++) {                                        \
            int qq_ = q_ld + (p_ & 3);                                          \
            cp16(da_ + r_ld * (LDA_ * 4) + qq_ * 16,                            \
                 A + (size_t)(row0 + r_ld) * K + k0_ + qq_ * 4);                \
            cp16(db_ + r_ld * (LDA_ * 4) + qq_ * 16,                            \
                 BT + (size_t)(col0 + r_ld) * K + k0_ + qq_ * 4);               \
        }                                                                       \
        CP_COMMIT();                                                            \
    } while (0)

    ISSUE(0, 0);
    for (int s = 0; s < S; s++) {
        int buf = s & 1;
        if (s + 1 < S) {
            ISSUE(s + 1, buf ^ 1);
            asm volatile("cp.async.wait_group 1;" ::: "memory");
        } else {
            asm volatile("cp.async.wait_group 0;" ::: "memory");
        }
        __syncthreads();

        const float* Ab = As + buf * 128 * LDA_;
        const float* Bb = Bs + buf * 128 * LDA_;
        #pragma unroll
        for (int ks = 0; ks < 4; ks++) {
            int kc = ks * 8 + tg;
            uint32_t af[4][4], bf[4][2];
            #pragma unroll
            for (int mi = 0; mi < 4; mi++) {
                const float* ap = Ab + (wr * 64 + mi * 16 + g) * LDA_ + kc;
                af[mi][0] = __float_as_uint(ap[0]);
                af[mi][1] = __float_as_uint(ap[8 * LDA_]);
                af[mi][2] = __float_as_uint(ap[4]);
                af[mi][3] = __float_as_uint(ap[8 * LDA_ + 4]);
            }
            #pragma unroll
            for (int ni = 0; ni < 4; ni++) {
                const float* bp = Bb + (wc * 32 + ni * 8 + g) * LDA_ + kc;
                bf[ni][0] = __float_as_uint(bp[0]);
                bf[ni][1] = __float_as_uint(bp[4]);
            }
            #pragma unroll
            for (int mi = 0; mi < 4; mi++)
                #pragma unroll
                for (int ni = 0; ni < 4; ni++)
                    mma_tf32(acc[mi][ni], af[mi], bf[ni]);
        }
        __syncthreads();
    }

    // epilogue
    #pragma unroll
    for (int mi = 0; mi < 4; mi++) {
        #pragma unroll
        for (int hh = 0; hh < 2; hh++) {
            int r = row0 + wr * 64 + mi * 16 + g + hh * 8;
            if (r >= M) continue;
            float* crow = C + (size_t)r * N;
            const float* arow = (epi == 2) ? (ADD + (size_t)r * N) : nullptr;
            #pragma unroll
            for (int ni = 0; ni < 4; ni++) {
                int c = col0 + wc * 32 + ni * 8 + tg * 2;
                float v0 = acc[mi][ni][hh * 2 + 0];
                float v1 = acc[mi][ni][hh * 2 + 1];
                if (epi == 1) {
                    v0 = 0.5f * v0 * (1.f + erff(v0 * 0.70710678118654752440f));
                    v1 = 0.5f * v1 * (1.f + erff(v1 * 0.70710678118654752440f));
                    v0 = rnd_tf32(v0); v1 = rnd_tf32(v1);
                } else if (epi == 2) {
                    v0 += arow[c]; v1 += arow[c + 1];
                }
                *(float2*)(crow + c) = make_float2(v0, v1);
            }
        }
    }
}

// ---------------------------------------------------------------------------
// Kernel 4a: growth EMA partial scans (zero init per 64-step segment)
// ---------------------------------------------------------------------------
__global__ __launch_bounds__(512) void growth_part(const float* __restrict__ z0,
        const float* __restrict__ sw) {
    int b = blockIdx.x, seg = blockIdx.y;
    int d = threadIdx.x;
    float w  = 1.f / (1.f + expf(-sw[d >> 6]));
    float om = 1.f - w;
    int t0 = seg * 64;
    const float* vp = g_v + ((size_t)b * T_ + t0) * D_ + d;
    float prev = (t0 == 0) ? z0[d] : vp[-(int)D_];
    float st = 0.f;
    float* gp = g_gpre + ((size_t)b * T1_ + t0 + 1) * D_ + d;
    #pragma unroll 8
    for (int t = 0; t < 64; t++) {
        float cur = vp[(size_t)t * D_];
        st = w * st + om * (cur - prev);
        prev = cur;
        gp[(size_t)t * D_] = st;
    }
    g_segf[((size_t)b * GSEG + seg) * D_ + d] = st;
}

// ---------------------------------------------------------------------------
// Kernel 4b: growth recombine + apply (out += w^(tl+1) * s_in), round tf32
// ---------------------------------------------------------------------------
__global__ __launch_bounds__(512) void growth_apply(const float* __restrict__ sw,
        const float* __restrict__ v0) {
    int b = blockIdx.x, seg = blockIdx.y;
    int d = threadIdx.x;
    float w = 1.f / (1.f + expf(-sw[d >> 6]));
    float w2 = w * w, w4 = w2 * w2, w8 = w4 * w4, w16 = w8 * w8, w32 = w16 * w16;
    float wL = w32 * w32;
    float s_in = v0[d];
    for (int j = 0; j < seg; j++)
        s_in = wL * s_in + g_segf[((size_t)b * GSEG + j) * D_ + d];
    if (seg == 0)
        g_gpre[((size_t)b * T1_) * D_ + d] = rnd_tf32(v0[d]);
    float* gp = g_gpre + ((size_t)b * T1_ + seg * 64 + 1) * D_ + d;
    float wp = w;
    #pragma unroll 8
    for (int t = 0; t < 64; t++) {
        gp[(size_t)t * D_] = rnd_tf32(gp[(size_t)t * D_] + wp * s_in);
        wp *= w;
    }
}

// ---------------------------------------------------------------------------
// Kernel 5: LayerNorm over D=512. If G: x = A_row - growth[b, t+1]. rnd: tf32
// ---------------------------------------------------------------------------
__global__ __launch_bounds__(128) void ln_k(const float* __restrict__ A,
        const float* __restrict__ G, const float* __restrict__ gam,
        const float* __restrict__ bet, float* __restrict__ out, int rnd) {
    __shared__ float sh[4], sh2[4];
    int row = blockIdx.x;
    int tid = threadIdx.x;
    const float* a = A + (size_t)row * D_;
    float x[4];
    if (G) {
        int b = row >> 10, t = row & 1023;
        const float* g = G + ((size_t)b * T1_ + t + 1) * D_;
        #pragma unroll
        for (int i = 0; i < 4; i++) x[i] = a[tid + i * 128] - g[tid + i * 128];
    } else {
        #pragma unroll
        for (int i = 0; i < 4; i++) x[i] = a[tid + i * 128];
    }
    float s = x[0] + x[1] + x[2] + x[3];
    #pragma unroll
    for (int o = 16; o; o >>= 1) s += __shfl_down_sync(0xffffffffu, s, o);
    if ((tid & 31) == 0) sh[tid >> 5] = s;
    __syncthreads();
    float mu = (sh[0] + sh[1] + sh[2] + sh[3]) * (1.f / 512.f);
    float vs = 0.f;
    #pragma unroll
    for (int i = 0; i < 4; i++) { float dx = x[i] - mu; vs += dx * dx; }
    #pragma unroll
    for (int o = 16; o; o >>= 1) vs += __shfl_down_sync(0xffffffffu, vs, o);
    if ((tid & 31) == 0) sh2[tid >> 5] = vs;
    __syncthreads();
    float var = (sh2[0] + sh2[1] + sh2[2] + sh2[3]) * (1.f / 512.f);
    float inv = rsqrtf(var + 1e-5f);
    float* o_ = out + (size_t)row * D_;
    #pragma unroll
    for (int i = 0; i < 4; i++) {
        int c = tid + i * 128;
        float v = (x[i] - mu) * inv * gam[c] + bet[c];
        o_[c] = rnd ? rnd_tf32(v) : v;
    }
}

// ---------------------------------------------------------------------------
// Kernel 6: skinny [*,512] @ [512,7]
// ---------------------------------------------------------------------------
__global__ __launch_bounds__(256) void skinny7(const float* __restrict__ X,
        size_t bstride, const float* __restrict__ W, float* __restrict__ out) {
    __shared__ float xs[512];
    int r = blockIdx.x;
    int b = r >> 10, t = r & 1023;
    const float* x = X + (size_t)b * bstride + (size_t)t * D_;
    for (int i = threadIdx.x; i < 512; i += 256) xs[i] = x[i];
    __syncthreads();
    int w = threadIdx.x >> 5, lane = threadIdx.x & 31;
    if (w < CO_) {
        float s = 0.f;
        for (int i = lane; i < 512; i += 32) s += xs[i] * W[i * CO_ + w];
        #pragma unroll
        for (int o = 16; o; o >>= 1) s += __shfl_down_sync(0xffffffffu, s, o);
        if (!lane) out[(size_t)r * CO_ + w] = s;
    }
}

// ---------------------------------------------------------------------------
// Kernel 7: level EMA scan with aux growth term
// ---------------------------------------------------------------------------
__global__ __launch_bounds__(128) void level_scan(const float* __restrict__ level,
        const float* __restrict__ lsw, const float* __restrict__ lv0,
        float* __restrict__ out) {
    int idx = threadIdx.x;
    if (idx >= B_ * CO_) return;
    int b = idx / CO_, c = idx % CO_;
    float w  = 1.f / (1.f + expf(-lsw[c]));
    float om = 1.f - w;
    float state = lv0[c];
    const float* lp = level + (size_t)b * T_ * CO_ + c;
    const float* sp = g_ss  + (size_t)b * T_ * CO_ + c;
    const float* gp = g_gg  + (size_t)b * T_ * CO_ + c;
    float*       op = out   + (size_t)b * T_ * CO_ + c;
    #pragma unroll 4
    for (int t = 0; t < T_; t++) {
        float val = lp[t * CO_] - sp[t * CO_];
        state = w * state + om * val + w * gp[t * CO_];
        op[t * CO_] = state;
    }
}

// ---------------------------------------------------------------------------
// Launch
// ---------------------------------------------------------------------------
extern "C" void kernel_launch(void* const* d_in, const int* in_sizes, int n_in,
                              void* d_out, int out_size) {
    const float* res  = (const float*)d_in[0];
    const float* lvl  = (const float*)d_in[1];
    const float* inw  = (const float*)d_in[2];
    const float* outw = (const float*)d_in[3];
    const float* z0   = (const float*)d_in[4];
    const float* gsw  = (const float*)d_in[5];
    const float* gv0  = (const float*)d_in[6];
    const float* ffw1 = (const float*)d_in[7];
    const float* ffw2 = (const float*)d_in[8];
    const float* n1g  = (const float*)d_in[9];
    const float* n1b  = (const float*)d_in[10];
    const float* n2g  = (const float*)d_in[11];
    const float* n2b  = (const float*)d_in[12];
    const float* gpw  = (const float*)d_in[13];
    const float* spw  = (const float*)d_in[14];
    const float* lsw  = (const float*)d_in[15];
    const float* lv0  = (const float*)d_in[16];

    float* out        = (float*)d_out;
    float* out_res3   = out;
    float* out_level  = out_res3  + (size_t)B_ * T_ * D_;
    float* out_growth = out_level + (size_t)B_ * T_ * CO_;
    float* out_season = out_growth + (size_t)B_ * T1_ * D_;

    float *p_res1, *p_v, *p_gpre, *p_res2, *p_hid, *p_pre, *p_gg, *p_ss;
    float *p_wtin, *p_wtout, *p_wtf1, *p_wtf2;
    cudaGetSymbolAddress((void**)&p_res1, g_res1);
    cudaGetSymbolAddress((void**)&p_v,    g_v);
    cudaGetSymbolAddress((void**)&p_gpre, g_gpre);
    cudaGetSymbolAddress((void**)&p_res2, g_res2);
    cudaGetSymbolAddress((void**)&p_hid,  g_hid);
    cudaGetSymbolAddress((void**)&p_pre,  g_pre);
    cudaGetSymbolAddress((void**)&p_gg,   g_gg);
    cudaGetSymbolAddress((void**)&p_ss,   g_ss);
    cudaGetSymbolAddress((void**)&p_wtin, g_wtin);
    cudaGetSymbolAddress((void**)&p_wtout, g_wtout);
    cudaGetSymbolAddress((void**)&p_wtf1, g_wtf1);
    cudaGetSymbolAddress((void**)&p_wtf2, g_wtf2);

    const int GSMEM = 2 * 2 * 128 * LDA_ * 4;   // 73728 bytes
    static int smem_set = 0;
    if (!smem_set) {
        cudaFuncSetAttribute(gemm_mma, cudaFuncAttributeMaxDynamicSharedMemorySize, GSMEM);
        smem_set = 1;
    }

    // 0. weight transposes (+tf32 rounding)
    transpose_rnd<<<dim3(D_ / 32, D_ / 32), 256>>>(inw,  p_wtin,  D_, D_);
    transpose_rnd<<<dim3(D_ / 32, D_ / 32), 256>>>(outw, p_wtout, D_, D_);
    transpose_rnd<<<dim3(LAT_ / 32, D_ / 32), 256>>>(ffw1, p_wtf1, D_, LAT_);
    transpose_rnd<<<dim3(D_ / 32, LAT_ / 32), 256>>>(ffw2, p_wtf2, LAT_, D_);
    // 1. FFT + top-k
    fft_topk<<<B_ * D_, 128>>>(res);
    // 2. season + res1 (tf32-rounded)
    season_k<<<dim3(D_ / 256, TP_ / 16, B_), 256>>>(res, out_season);
    // 3. v = res1 @ in_w   (tensor core)
    gemm_mma<<<dim3(D_ / 128, (B_ * T_) / 128), 256, GSMEM>>>(
        B_ * T_, D_, D_, p_res1, p_wtin, p_v, 0, nullptr);
    // 4. growth EMA: segmented scan
    growth_part<<<dim3(B_, GSEG), 512>>>(z0, gsw);
    growth_apply<<<dim3(B_, GSEG), 512>>>(gsw, gv0);
    // 5. growth = gpre @ out_w
    gemm_mma<<<dim3(D_ / 128, (B_ * T1_ + 127) / 128), 256, GSMEM>>>(
        B_ * T1_, D_, D_, p_gpre, p_wtout, out_growth, 0, nullptr);
    // 6. res2 = LN1(res1 - growth[:,1:])  (tf32-rounded)
    ln_k<<<B_ * T_, 128>>>(p_res1, out_growth, n1g, n1b, p_res2, 1);
    // 7. hid = gelu(res2 @ ff_w1)  (tf32-rounded in epilogue)
    gemm_mma<<<dim3(LAT_ / 128, (B_ * T_) / 128), 256, GSMEM>>>(
        B_ * T_, LAT_, D_, p_res2, p_wtf1, p_hid, 1, nullptr);
    // 8. pre = hid @ ff_w2 + res2
    gemm_mma<<<dim3(D_ / 128, (B_ * T_) / 128), 256, GSMEM>>>(
        B_ * T_, D_, LAT_, p_hid, p_wtf2, p_pre, 2, p_res2);
    // 9. res3 = LN2(pre)
    ln_k<<<B_ * T_, 128>>>(p_pre, nullptr, n2g, n2b, out_res3, 0);
    // 10. skinny projections
    skinny7<<<B_ * T_, 256>>>(out_growth, (size_t)T1_ * D_, gpw, p_gg);
    skinny7<<<B_ * T_, 256>>>(out_season, (size_t)TP_ * D_, spw, p_ss);
    // 11. level EMA scan
    level_scan<<<1, 128>>>(lvl, lsw, lv0, out_level);
}

// round 8
// speedup vs baseline: 2.6290x; 1.2280x over previous
#include <cuda_runtime.h>
#include <math.h>
#include <stdint.h>

// ---------------------------------------------------------------------------
// Problem constants
// ---------------------------------------------------------------------------
#define B_   16
#define T_   1024
#define D_   512
#define CO_  7
#define PRED_ 96
#define K_   8
#define LAT_ 2048
#define TP_  (T_ + PRED_)   // 1120
#define T1_  (T_ + 1)       // 1025
#define GSEG 16             // growth scan segments (64 steps each)
#define MPAD_G 16512        // 129*128 padded rows for growth GEMM

// ---------------------------------------------------------------------------
// Static device scratch
// ---------------------------------------------------------------------------
__device__ float g_res1[(size_t)B_ * T_ * D_];
__device__ float g_rest[(size_t)B_ * D_ * T_];         // res transposed [b][d][t]
__device__ float g_v   [(size_t)B_ * T_ * D_];
__device__ float g_gpre[(size_t)MPAD_G * D_];          // padded rows (pad stays 0)
__device__ float g_res2[(size_t)B_ * T_ * D_];
__device__ float g_hid [(size_t)B_ * T_ * LAT_];
__device__ float g_pre [(size_t)B_ * T_ * D_];
__device__ float g_gg  [(size_t)B_ * T_ * CO_];
__device__ float g_ss  [(size_t)B_ * T_ * CO_];
__device__ float g_tk  [3 * K_ * B_ * D_];
__device__ float g_segf[(size_t)B_ * GSEG * D_];       // growth segment finals
// transposed + tf32-rounded weights [N][K]
__device__ float g_wtin [(size_t)D_ * D_];
__device__ float g_wtout[(size_t)D_ * D_];
__device__ float g_wtf1 [(size_t)LAT_ * D_];
__device__ float g_wtf2 [(size_t)D_ * LAT_];

// ---------------------------------------------------------------------------
// Helpers
// ---------------------------------------------------------------------------
__device__ __forceinline__ uint32_t smem_u32(const void* p) {
    uint32_t a;
    asm("{ .reg .u64 t; cvta.to.shared.u64 t, %1; cvt.u32.u64 %0, t; }" : "=r"(a) : "l"(p));
    return a;
}
__device__ __forceinline__ float rnd_tf32(float x) {
    uint32_t o;
    asm("cvt.rna.tf32.f32 %0, %1;" : "=r"(o) : "f"(x));
    return __uint_as_float(o);
}
__device__ __forceinline__ void cp16(uint32_t dst, const void* src) {
    asm volatile("cp.async.cg.shared.global [%0], [%1], 16;" :: "r"(dst), "l"(src));
}
#define CP_COMMIT() asm volatile("cp.async.commit_group;" ::: "memory")

__device__ __forceinline__ void mma_tf32(float* c, const uint32_t* a, const uint32_t* b) {
    asm volatile(
        "mma.sync.aligned.m16n8k8.row.col.f32.tf32.tf32.f32 "
        "{%0,%1,%2,%3}, {%4,%5,%6,%7}, {%8,%9}, {%0,%1,%2,%3};"
        : "+f"(c[0]), "+f"(c[1]), "+f"(c[2]), "+f"(c[3])
        : "r"(a[0]), "r"(a[1]), "r"(a[2]), "r"(a[3]), "r"(b[0]), "r"(b[1]));
}
__device__ __forceinline__ void ldsm4(uint32_t* r, uint32_t addr) {
    asm volatile("ldmatrix.sync.aligned.m8n8.x4.shared.b16 {%0,%1,%2,%3}, [%4];"
        : "=r"(r[0]), "=r"(r[1]), "=r"(r[2]), "=r"(r[3]) : "r"(addr));
}

// ---------------------------------------------------------------------------
// Kernel: weight transpose [K,N] -> [N,K] with tf32 RN rounding
// ---------------------------------------------------------------------------
__global__ __launch_bounds__(256) void transpose_rnd(const float* __restrict__ W,
        float* __restrict__ WT, int K, int N) {
    __shared__ float t[32][33];
    int n0 = blockIdx.x * 32, k0 = blockIdx.y * 32;
    int tx = threadIdx.x & 31, ty = threadIdx.x >> 5;   // 32x8
    #pragma unroll
    for (int i = 0; i < 32; i += 8)
        t[ty + i][tx] = W[(size_t)(k0 + ty + i) * N + n0 + tx];
    __syncthreads();
    #pragma unroll
    for (int i = 0; i < 32; i += 8)
        WT[(size_t)(n0 + ty + i) * K + k0 + tx] = rnd_tf32(t[tx][ty + i]);
}

// ---------------------------------------------------------------------------
// Kernel: res transpose [b][t][d] -> [b][d][t] (coalesced FFT input)
// ---------------------------------------------------------------------------
__global__ __launch_bounds__(256) void transpose_res(const float* __restrict__ X) {
    __shared__ float t[32][33];
    int d0 = blockIdx.x * 32, t0 = blockIdx.y * 32, b = blockIdx.z;
    int tx = threadIdx.x & 31, ty = threadIdx.x >> 5;
    #pragma unroll
    for (int i = 0; i < 32; i += 8)
        t[ty + i][tx] = X[((size_t)b * T_ + t0 + ty + i) * D_ + d0 + tx];
    __syncthreads();
    #pragma unroll
    for (int i = 0; i < 32; i += 8)
        g_rest[((size_t)b * D_ + d0 + ty + i) * T_ + t0 + tx] = t[tx][ty + i];
}

// ---------------------------------------------------------------------------
// Kernel 1: per-(b,d) 1024-pt radix-2 FFT + top-8 selection
//   input: g_rest (contiguous time series per (b,d)); smem twiddle table
// ---------------------------------------------------------------------------
__global__ __launch_bounds__(128) void fft_topk() {
    __shared__ float re[1024], im[1024], mag[512];
    __shared__ float twr[512], twi[512];
    __shared__ float wbv[4];
    __shared__ int   wbi[4];
    int bd  = blockIdx.x;
    int tid = threadIdx.x;
    const float* x = g_rest + (size_t)bd * T_;

    // twiddle table: W_1024^i = exp(-2*pi*i*j/1024); same float args as sincosf path
    for (int i = tid; i < 512; i += 128) {
        float s_, c_;
        sincosf(-6.28318530717958647692f * ((float)i * (1.f / 1024.f)), &s_, &c_);
        twi[i] = s_; twr[i] = c_;
    }
    // load, bit-reversed (10 bits), imag = 0  (coalesced global read)
    for (int t = tid; t < 1024; t += 128) {
        int r = __brev((unsigned)t) >> 22;
        re[r] = x[t];
        im[r] = 0.f;
    }
    __syncthreads();

    for (int s = 1; s <= 10; s++) {
        int half = 1 << (s - 1);
        int shift = 10 - s;
        for (int j = tid; j < 512; j += 128) {
            int k  = j & (half - 1);
            int i0 = ((j >> (s - 1)) << s) + k;
            int i1 = i0 + half;
            int ti = k << shift;
            float wr_ = twr[ti], wi_ = twi[ti];
            float ar = re[i1], ai = im[i1];
            float tr = wr_ * ar - wi_ * ai;
            float tii = wr_ * ai + wi_ * ar;
            float br = re[i0], bi = im[i0];
            re[i0] = br + tr; im[i0] = bi + tii;
            re[i1] = br - tr; im[i1] = bi - tii;
        }
        __syncthreads();
    }

    for (int f = tid; f < 512; f += 128)
        mag[f] = (f == 0) ? -1.f : re[f] * re[f] + im[f] * im[f];
    __syncthreads();

    for (int kk = 0; kk < K_; kk++) {
        float best = -2.f; int bidx = 0;
        for (int f = tid; f < 512; f += 128) {
            float m = mag[f];
            if (m > best) { best = m; bidx = f; }
        }
        #pragma unroll
        for (int o = 16; o; o >>= 1) {
            float ob = __shfl_down_sync(0xffffffffu, best, o);
            int   oi = __shfl_down_sync(0xffffffffu, bidx, o);
            if (ob > best) { best = ob; bidx = oi; }
        }
        if ((tid & 31) == 0) { wbv[tid >> 5] = best; wbi[tid >> 5] = bidx; }
        __syncthreads();
        if (tid == 0) {
            for (int w = 1; w < 4; w++)
                if (wbv[w] > best) { best = wbv[w]; bidx = wbi[w]; }
            float rr = re[bidx], ii = im[bidx];
            g_tk[(0 * K_ + kk) * (B_ * D_) + bd] = 2.f * sqrtf(best) * (1.f / 1024.f);
            g_tk[(1 * K_ + kk) * (B_ * D_) + bd] =
                6.28318530717958647692f * ((float)bidx * (1.f / 1024.f));
            g_tk[(2 * K_ + kk) * (B_ * D_) + bd] = atan2f(ii, rr);
            mag[bidx] = -1.f;
        }
        __syncthreads();
    }
}

// ---------------------------------------------------------------------------
// Kernel 2: season synthesis + res1 = res - season (rounded to tf32)
// ---------------------------------------------------------------------------
__global__ __launch_bounds__(256) void season_k(const float* __restrict__ res,
                                                float* __restrict__ season_out) {
    __shared__ float sa[K_][256], sc[K_][256], sp[K_][256];
    int tid = threadIdx.x;
    int d   = blockIdx.x * 256 + tid;
    int b   = blockIdx.z;
    int bd  = b * D_ + d;
    #pragma unroll
    for (int k = 0; k < K_; k++) {
        sa[k][tid] = g_tk[(0 * K_ + k) * (B_ * D_) + bd];
        sc[k][tid] = g_tk[(1 * K_ + k) * (B_ * D_) + bd];
        sp[k][tid] = g_tk[(2 * K_ + k) * (B_ * D_) + bd];
    }
    __syncthreads();
    int t0 = blockIdx.y * 16;
    for (int tt = 0; tt < 16; tt++) {
        int t = t0 + tt;
        float tf = (float)t;
        float sum = 0.f;
        #pragma unroll
        for (int k = 0; k < K_; k++) {
            float a = __fadd_rn(__fmul_rn(sc[k][tid], tf), sp[k][tid]);
            sum += sa[k][tid] * cosf(a);
        }
        season_out[((size_t)b * TP_ + t) * D_ + d] = sum;
        if (t < T_) {
            size_t ro = ((size_t)b * T_ + t) * D_ + d;
            g_res1[ro] = rnd_tf32(res[ro] - sum);
        }
    }
}

// ---------------------------------------------------------------------------
// Kernel 3: tf32 mma.sync GEMM, ldmatrix fragments, 3-stage cp.async.
//   CTA tile 128 x (64*WC); warp grid 2 x WC, warp tile 64x64.
//   C[M,N] = A[M,K] @ BT[N,K]^T ;  epi: 0 none, 1 gelu(+tf32 rnd), 2 +ADD
// ---------------------------------------------------------------------------
template<int WC>
__global__ void __launch_bounds__(WC * 64, (WC == 2) ? 2 : 1)
gemm_mma(int M, int N, int K,
         const float* __restrict__ A, const float* __restrict__ BT,
         float* __restrict__ C, int epi, const float* __restrict__ ADD) {
    constexpr int NT = WC * 64;                 // CTA N-tile
    constexpr int THREADS = WC * 64;
    constexpr int STAGE_B = (128 + NT) * 36 * 4;  // bytes per stage
    extern __shared__ float smf[];
    uint32_t s0 = smem_u32(smf);

    int tid = threadIdx.x, wid = tid >> 5, lane = tid & 31;
    int wr = wid / WC, wc = wid % WC;
    int g = lane >> 2, tg = lane & 3;
    int row0 = blockIdx.y * 128, col0 = blockIdx.x * NT;

    // per-thread ldmatrix row/col offsets (x4 submatrix mapping)
    int a_r = wr * 64 + ((lane >> 3) & 1) * 8 + (lane & 7);
    int a_c = (lane >> 4) * 4;
    int b_r = wc * 64 + (lane >> 4) * 8 + (lane & 7);
    int b_c = ((lane >> 3) & 1) * 4;

    float acc[4][8][4] = {};
    const int S = K >> 5;

    auto issue = [&](int s, int buf) {
        int k0 = s * 32;
        uint32_t da = s0 + buf * STAGE_B;
        uint32_t db = da + 128 * 36 * 4;
        #pragma unroll
        for (int p = 0; p < 1024 / THREADS; p++) {
            int c = tid + p * THREADS;
            int r = c >> 3, q = c & 7;
            cp16(da + r * 144 + q * 16, A + (size_t)(row0 + r) * K + k0 + q * 4);
        }
        #pragma unroll
        for (int p = 0; p < NT * 8 / THREADS; p++) {
            int c = tid + p * THREADS;
            int r = c >> 3, q = c & 7;
            cp16(db + r * 144 + q * 16, BT + (size_t)(col0 + r) * K + k0 + q * 4);
        }
        CP_COMMIT();
    };

    issue(0, 0);
    if (S > 1) issue(1, 1);
    for (int s = 0; s < S; s++) {
        int buf = s % 3;
        if (s + 2 < S) {
            issue(s + 2, (s + 2) % 3);
            asm volatile("cp.async.wait_group 2;" ::: "memory");
        } else if (s + 1 < S) {
            asm volatile("cp.async.wait_group 1;" ::: "memory");
        } else {
            asm volatile("cp.async.wait_group 0;" ::: "memory");
        }
        __syncthreads();
        uint32_t sa = s0 + buf * STAGE_B;
        uint32_t sb = sa + 128 * 36 * 4;
        #pragma unroll
        for (int ks = 0; ks < 4; ks++) {
            uint32_t af[4][4], bf[8][2];
            #pragma unroll
            for (int mi = 0; mi < 4; mi++)
                ldsm4(af[mi], sa + (uint32_t)(((a_r + mi * 16) * 36 + ks * 8 + a_c) * 4));
            #pragma unroll
            for (int np = 0; np < 4; np++) {
                uint32_t tb[4];
                ldsm4(tb, sb + (uint32_t)(((b_r + np * 16) * 36 + ks * 8 + b_c) * 4));
                bf[2 * np][0] = tb[0]; bf[2 * np][1] = tb[1];
                bf[2 * np + 1][0] = tb[2]; bf[2 * np + 1][1] = tb[3];
            }
            #pragma unroll
            for (int mi = 0; mi < 4; mi++)
                #pragma unroll
                for (int ni = 0; ni < 8; ni++)
                    mma_tf32(acc[mi][ni], af[mi], bf[ni]);
        }
        __syncthreads();
    }

    // epilogue
    #pragma unroll
    for (int mi = 0; mi < 4; mi++) {
        #pragma unroll
        for (int hh = 0; hh < 2; hh++) {
            int r = row0 + wr * 64 + mi * 16 + g + hh * 8;
            if (r >= M) continue;
            float* crow = C + (size_t)r * N;
            const float* arow = (epi == 2) ? (ADD + (size_t)r * N) : nullptr;
            #pragma unroll
            for (int ni = 0; ni < 8; ni++) {
                int c = col0 + wc * 64 + ni * 8 + tg * 2;
                float v0 = acc[mi][ni][hh * 2 + 0];
                float v1 = acc[mi][ni][hh * 2 + 1];
                if (epi == 1) {
                    v0 = 0.5f * v0 * (1.f + erff(v0 * 0.70710678118654752440f));
                    v1 = 0.5f * v1 * (1.f + erff(v1 * 0.70710678118654752440f));
                    v0 = rnd_tf32(v0); v1 = rnd_tf32(v1);
                } else if (epi == 2) {
                    v0 += arow[c]; v1 += arow[c + 1];
                }
                *(float2*)(crow + c) = make_float2(v0, v1);
            }
        }
    }
}

// ---------------------------------------------------------------------------
// Kernel 4a: growth EMA partial scans (zero init per 64-step segment)
// ---------------------------------------------------------------------------
__global__ __launch_bounds__(512) void growth_part(const float* __restrict__ z0,
        const float* __restrict__ sw) {
    int b = blockIdx.x, seg = blockIdx.y;
    int d = threadIdx.x;
    float w  = 1.f / (1.f + expf(-sw[d >> 6]));
    float om = 1.f - w;
    int t0 = seg * 64;
    const float* vp = g_v + ((size_t)b * T_ + t0) * D_ + d;
    float prev = (t0 == 0) ? z0[d] : vp[-(int)D_];
    float st = 0.f;
    float* gp = g_gpre + ((size_t)b * T1_ + t0 + 1) * D_ + d;
    #pragma unroll 8
    for (int t = 0; t < 64; t++) {
        float cur = vp[(size_t)t * D_];
        st = w * st + om * (cur - prev);
        prev = cur;
        gp[(size_t)t * D_] = st;
    }
    g_segf[((size_t)b * GSEG + seg) * D_ + d] = st;
}

// ---------------------------------------------------------------------------
// Kernel 4b: growth recombine + apply (out += w^(tl+1) * s_in), round tf32
// ---------------------------------------------------------------------------
__global__ __launch_bounds__(512) void growth_apply(const float* __restrict__ sw,
        const float* __restrict__ v0) {
    int b = blockIdx.x, seg = blockIdx.y;
    int d = threadIdx.x;
    float w = 1.f / (1.f + expf(-sw[d >> 6]));
    float w2 = w * w, w4 = w2 * w2, w8 = w4 * w4, w16 = w8 * w8, w32 = w16 * w16;
    float wL = w32 * w32;
    float s_in = v0[d];
    for (int j = 0; j < seg; j++)
        s_in = wL * s_in + g_segf[((size_t)b * GSEG + j) * D_ + d];
    if (seg == 0)
        g_gpre[((size_t)b * T1_) * D_ + d] = rnd_tf32(v0[d]);
    float* gp = g_gpre + ((size_t)b * T1_ + seg * 64 + 1) * D_ + d;
    float wp = w;
    #pragma unroll 8
    for (int t = 0; t < 64; t++) {
        gp[(size_t)t * D_] = rnd_tf32(gp[(size_t)t * D_] + wp * s_in);
        wp *= w;
    }
}

// ---------------------------------------------------------------------------
// Kernel 5: LayerNorm over D=512. If G: x = A_row - growth[b, t+1]. rnd: tf32
// ---------------------------------------------------------------------------
__global__ __launch_bounds__(128) void ln_k(const float* __restrict__ A,
        const float* __restrict__ G, const float* __restrict__ gam,
        const float* __restrict__ bet, float* __restrict__ out, int rnd) {
    __shared__ float sh[4], sh2[4];
    int row = blockIdx.x;
    int tid = threadIdx.x;
    const float* a = A + (size_t)row * D_;
    float x[4];
    if (G) {
        int b = row >> 10, t = row & 1023;
        const float* g = G + ((size_t)b * T1_ + t + 1) * D_;
        #pragma unroll
        for (int i = 0; i < 4; i++) x[i] = a[tid + i * 128] - g[tid + i * 128];
    } else {
        #pragma unroll
        for (int i = 0; i < 4; i++) x[i] = a[tid + i * 128];
    }
    float s = x[0] + x[1] + x[2] + x[3];
    #pragma unroll
    for (int o = 16; o; o >>= 1) s += __shfl_down_sync(0xffffffffu, s, o);
    if ((tid & 31) == 0) sh[tid >> 5] = s;
    __syncthreads();
    float mu = (sh[0] + sh[1] + sh[2] + sh[3]) * (1.f / 512.f);
    float vs = 0.f;
    #pragma unroll
    for (int i = 0; i < 4; i++) { float dx = x[i] - mu; vs += dx * dx; }
    #pragma unroll
    for (int o = 16; o; o >>= 1) vs += __shfl_down_sync(0xffffffffu, vs, o);
    if ((tid & 31) == 0) sh2[tid >> 5] = vs;
    __syncthreads();
    float var = (sh2[0] + sh2[1] + sh2[2] + sh2[3]) * (1.f / 512.f);
    float inv = rsqrtf(var + 1e-5f);
    float* o_ = out + (size_t)row * D_;
    #pragma unroll
    for (int i = 0; i < 4; i++) {
        int c = tid + i * 128;
        float v = (x[i] - mu) * inv * gam[c] + bet[c];
        o_[c] = rnd ? rnd_tf32(v) : v;
    }
}

// ---------------------------------------------------------------------------
// Kernel 6: skinny [*,512] @ [512,7]
// ---------------------------------------------------------------------------
__global__ __launch_bounds__(256) void skinny7(const float* __restrict__ X,
        size_t bstride, const float* __restrict__ W, float* __restrict__ out) {
    __shared__ float xs[512];
    int r = blockIdx.x;
    int b = r >> 10, t = r & 1023;
    const float* x = X + (size_t)b * bstride + (size_t)t * D_;
    for (int i = threadIdx.x; i < 512; i += 256) xs[i] = x[i];
    __syncthreads();
    int w = threadIdx.x >> 5, lane = threadIdx.x & 31;
    if (w < CO_) {
        float s = 0.f;
        for (int i = lane; i < 512; i += 32) s += xs[i] * W[i * CO_ + w];
        #pragma unroll
        for (int o = 16; o; o >>= 1) s += __shfl_down_sync(0xffffffffu, s, o);
        if (!lane) out[(size_t)r * CO_ + w] = s;
    }
}

// ---------------------------------------------------------------------------
// Kernel 7: level EMA scan with aux growth term
// ---------------------------------------------------------------------------
__global__ __launch_bounds__(128) void level_scan(const float* __restrict__ level,
        const float* __restrict__ lsw, const float* __restrict__ lv0,
        float* __restrict__ out) {
    int idx = threadIdx.x;
    if (idx >= B_ * CO_) return;
    int b = idx / CO_, c = idx % CO_;
    float w  = 1.f / (1.f + expf(-lsw[c]));
    float om = 1.f - w;
    float state = lv0[c];
    const float* lp = level + (size_t)b * T_ * CO_ + c;
    const float* sp = g_ss  + (size_t)b * T_ * CO_ + c;
    const float* gp = g_gg  + (size_t)b * T_ * CO_ + c;
    float*       op = out   + (size_t)b * T_ * CO_ + c;
    #pragma unroll 4
    for (int t = 0; t < T_; t++) {
        float val = lp[t * CO_] - sp[t * CO_];
        state = w * state + om * val + w * gp[t * CO_];
        op[t * CO_] = state;
    }
}

// ---------------------------------------------------------------------------
// Launch
// ---------------------------------------------------------------------------
extern "C" void kernel_launch(void* const* d_in, const int* in_sizes, int n_in,
                              void* d_out, int out_size) {
    const float* res  = (const float*)d_in[0];
    const float* lvl  = (const float*)d_in[1];
    const float* inw  = (const float*)d_in[2];
    const float* outw = (const float*)d_in[3];
    const float* z0   = (const float*)d_in[4];
    const float* gsw  = (const float*)d_in[5];
    const float* gv0  = (const float*)d_in[6];
    const float* ffw1 = (const float*)d_in[7];
    const float* ffw2 = (const float*)d_in[8];
    const float* n1g  = (const float*)d_in[9];
    const float* n1b  = (const float*)d_in[10];
    const float* n2g  = (const float*)d_in[11];
    const float* n2b  = (const float*)d_in[12];
    const float* gpw  = (const float*)d_in[13];
    const float* spw  = (const float*)d_in[14];
    const float* lsw  = (const float*)d_in[15];
    const float* lv0  = (const float*)d_in[16];

    float* out        = (float*)d_out;
    float* out_res3   = out;
    float* out_level  = out_res3  + (size_t)B_ * T_ * D_;
    float* out_growth = out_level + (size_t)B_ * T_ * CO_;
    float* out_season = out_growth + (size_t)B_ * T1_ * D_;

    float *p_res1, *p_v, *p_gpre, *p_res2, *p_hid, *p_pre, *p_gg, *p_ss;
    float *p_wtin, *p_wtout, *p_wtf1, *p_wtf2;
    cudaGetSymbolAddress((void**)&p_res1, g_res1);
    cudaGetSymbolAddress((void**)&p_v,    g_v);
    cudaGetSymbolAddress((void**)&p_gpre, g_gpre);
    cudaGetSymbolAddress((void**)&p_res2, g_res2);
    cudaGetSymbolAddress((void**)&p_hid,  g_hid);
    cudaGetSymbolAddress((void**)&p_pre,  g_pre);
    cudaGetSymbolAddress((void**)&p_gg,   g_gg);
    cudaGetSymbolAddress((void**)&p_ss,   g_ss);
    cudaGetSymbolAddress((void**)&p_wtin, g_wtin);
    cudaGetSymbolAddress((void**)&p_wtout, g_wtout);
    cudaGetSymbolAddress((void**)&p_wtf1, g_wtf1);
    cudaGetSymbolAddress((void**)&p_wtf2, g_wtf2);

    const int SMEM4 = 3 * (128 + 256) * 36 * 4;   // 165888
    const int SMEM2 = 3 * (128 + 128) * 36 * 4;   // 82944
    static int smem_set = 0;
    if (!smem_set) {
        cudaFuncSetAttribute(gemm_mma<4>, cudaFuncAttributeMaxDynamicSharedMemorySize, SMEM4);
        cudaFuncSetAttribute(gemm_mma<2>, cudaFuncAttributeMaxDynamicSharedMemorySize, SMEM2);
        smem_set = 1;
    }

    // 0. weight transposes (+tf32 rounding), res transpose for FFT
    transpose_rnd<<<dim3(D_ / 32, D_ / 32), 256>>>(inw,  p_wtin,  D_, D_);
    transpose_rnd<<<dim3(D_ / 32, D_ / 32), 256>>>(outw, p_wtout, D_, D_);
    transpose_rnd<<<dim3(LAT_ / 32, D_ / 32), 256>>>(ffw1, p_wtf1, D_, LAT_);
    transpose_rnd<<<dim3(D_ / 32, LAT_ / 32), 256>>>(ffw2, p_wtf2, LAT_, D_);
    transpose_res<<<dim3(D_ / 32, T_ / 32, B_), 256>>>(res);
    // 1. FFT + top-k (coalesced input, twiddle tables)
    fft_topk<<<B_ * D_, 128>>>();
    // 2. season + res1 (tf32-rounded)
    season_k<<<dim3(D_ / 256, TP_ / 16, B_), 256>>>(res, out_season);
    // 3. v = res1 @ in_w
    gemm_mma<2><<<dim3(D_ / 128, (B_ * T_) / 128), 128, SMEM2>>>(
        B_ * T_, D_, D_, p_res1, p_wtin, p_v, 0, nullptr);
    // 4. growth EMA: segmented scan
    growth_part<<<dim3(B_, GSEG), 512>>>(z0, gsw);
    growth_apply<<<dim3(B_, GSEG), 512>>>(gsw, gv0);
    // 5. growth = gpre @ out_w
    gemm_mma<2><<<dim3(D_ / 128, (B_ * T1_ + 127) / 128), 128, SMEM2>>>(
        B_ * T1_, D_, D_, p_gpre, p_wtout, out_growth, 0, nullptr);
    // 6. res2 = LN1(res1 - growth[:,1:])  (tf32-rounded)
    ln_k<<<B_ * T_, 128>>>(p_res1, out_growth, n1g, n1b, p_res2, 1);
    // 7. hid = gelu(res2 @ ff_w1)  (tf32-rounded in epilogue)
    gemm_mma<4><<<dim3(LAT_ / 256, (B_ * T_) / 128), 256, SMEM4>>>(
        B_ * T_, LAT_, D_, p_res2, p_wtf1, p_hid, 1, nullptr);
    // 8. pre = hid @ ff_w2 + res2
    gemm_mma<2><<<dim3(D_ / 128, (B_ * T_) / 128), 128, SMEM2>>>(
        B_ * T_, D_, LAT_, p_hid, p_wtf2, p_pre, 2, p_res2);
    // 9. res3 = LN2(pre)
    ln_k<<<B_ * T_, 128>>>(p_pre, nullptr, n2g, n2b, out_res3, 0);
    // 10. skinny projections
    skinny7<<<B_ * T_, 256>>>(out_growth, (size_t)T1_ * D_, gpw, p_gg);
    skinny7<<<B_ * T_, 256>>>(out_season, (size_t)TP_ * D_, spw, p_ss);
    // 11. level EMA scan
    level_scan<<<1, 128>>>(lvl, lsw, lv0, out_level);
}

// round 11
// speedup vs baseline: 3.1108x; 1.1833x over previous
#include <cuda_runtime.h>
#include <cuda_fp16.h>
#include <math.h>
#include <stdint.h>

// ---------------------------------------------------------------------------
// Problem constants
// ---------------------------------------------------------------------------
#define B_   16
#define T_   1024
#define D_   512
#define CO_  7
#define PRED_ 96
#define K_   8
#define LAT_ 2048
#define TP_  (T_ + PRED_)   // 1120
#define T1_  (T_ + 1)       // 1025
#define GSEG 16             // growth scan segments (64 steps each)
#define MPAD_G 16512        // 129*128 padded rows for growth GEMM

// ---------------------------------------------------------------------------
// Static device scratch
// ---------------------------------------------------------------------------
__device__ float  g_res1f[(size_t)B_ * T_ * D_];
__device__ __half g_res1h[(size_t)B_ * T_ * D_];
__device__ float  g_rest [(size_t)B_ * D_ * T_];        // res transposed [b][d][t]
__device__ float  g_v    [(size_t)B_ * T_ * D_];
__device__ float  g_gtmp [(size_t)B_ * T_ * D_];        // growth partial states (fp32)
__device__ __half g_gpre [(size_t)MPAD_G * D_];         // half GEMM input (pad = 0)
__device__ float  g_res2f[(size_t)B_ * T_ * D_];
__device__ __half g_res2h[(size_t)B_ * T_ * D_];
__device__ __half g_hid  [(size_t)B_ * T_ * LAT_];
__device__ float  g_pre  [(size_t)B_ * T_ * D_];
__device__ float  g_gg   [(size_t)B_ * T_ * CO_];
__device__ float  g_ss   [(size_t)B_ * T_ * CO_];
__device__ float  g_tkA  [K_ * B_ * D_];                // re/512
__device__ float  g_tkB  [K_ * B_ * D_];                // im/512
__device__ int    g_tki  [K_ * B_ * D_];                // freq bin index
__device__ float  g_segf [(size_t)B_ * GSEG * D_];
// transposed + fp16-rounded weights [N][K]
__device__ __half g_win [(size_t)D_ * D_];
__device__ __half g_wout[(size_t)D_ * D_];
__device__ __half g_wf1 [(size_t)LAT_ * D_];
__device__ __half g_wf2 [(size_t)D_ * LAT_];

// ---------------------------------------------------------------------------
// Helpers
// ---------------------------------------------------------------------------
__device__ __forceinline__ uint32_t smem_u32(const void* p) {
    uint32_t a;
    asm("{ .reg .u64 t; cvta.to.shared.u64 t, %1; cvt.u32.u64 %0, t; }" : "=r"(a) : "l"(p));
    return a;
}
__device__ __forceinline__ void cp16(uint32_t dst, const void* src) {
    asm volatile("cp.async.cg.shared.global [%0], [%1], 16;" :: "r"(dst), "l"(src));
}
#define CP_COMMIT() asm volatile("cp.async.commit_group;" ::: "memory")

__device__ __forceinline__ void mma_f16(float* c, const uint32_t* a, const uint32_t* b) {
    asm volatile(
        "mma.sync.aligned.m16n8k16.row.col.f32.f16.f16.f32 "
        "{%0,%1,%2,%3}, {%4,%5,%6,%7}, {%8,%9}, {%0,%1,%2,%3};"
        : "+f"(c[0]), "+f"(c[1]), "+f"(c[2]), "+f"(c[3])
        : "r"(a[0]), "r"(a[1]), "r"(a[2]), "r"(a[3]), "r"(b[0]), "r"(b[1]));
}
__device__ __forceinline__ void ldsm4(uint32_t* r, uint32_t addr) {
    asm volatile("ldmatrix.sync.aligned.m8n8.x4.shared.b16 {%0,%1,%2,%3}, [%4];"
        : "=r"(r[0]), "=r"(r[1]), "=r"(r[2]), "=r"(r[3]) : "r"(addr));
}

// ---------------------------------------------------------------------------
// Kernel: weight transpose [K,N] -> [N,K], rounded fp32 -> fp16
// ---------------------------------------------------------------------------
__global__ __launch_bounds__(256) void transpose_h(const float* __restrict__ W,
        __half* __restrict__ WT, int K, int N) {
    __shared__ float t[32][33];
    int n0 = blockIdx.x * 32, k0 = blockIdx.y * 32;
    int tx = threadIdx.x & 31, ty = threadIdx.x >> 5;   // 32x8
    #pragma unroll
    for (int i = 0; i < 32; i += 8)
        t[ty + i][tx] = W[(size_t)(k0 + ty + i) * N + n0 + tx];
    __syncthreads();
    #pragma unroll
    for (int i = 0; i < 32; i += 8)
        WT[(size_t)(n0 + ty + i) * K + k0 + tx] = __float2half_rn(t[tx][ty + i]);
}

// ---------------------------------------------------------------------------
// Kernel: res transpose [b][t][d] -> [b][d][t] (coalesced FFT input)
// ---------------------------------------------------------------------------
__global__ __launch_bounds__(256) void transpose_res(const float* __restrict__ X) {
    __shared__ float t[32][33];
    int d0 = blockIdx.x * 32, t0 = blockIdx.y * 32, b = blockIdx.z;
    int tx = threadIdx.x & 31, ty = threadIdx.x >> 5;
    #pragma unroll
    for (int i = 0; i < 32; i += 8)
        t[ty + i][tx] = X[((size_t)b * T_ + t0 + ty + i) * D_ + d0 + tx];
    __syncthreads();
    #pragma unroll
    for (int i = 0; i < 32; i += 8)
        g_rest[((size_t)b * D_ + d0 + ty + i) * T_ + t0 + tx] = t[tx][ty + i];
}

// ---------------------------------------------------------------------------
// Kernel 1: per-(b,d) 1024-pt radix-2 FFT + top-8 selection (256 threads)
//   stores A = re/512, B = im/512, idx (no atan2/sqrt needed downstream)
// ---------------------------------------------------------------------------
__global__ __launch_bounds__(256) void fft_topk() {
    __shared__ float re[1024], im[1024], mag[512];
    __shared__ float twr[512], twi[512];
    __shared__ float wbv[8];
    __shared__ int   wbi[8];
    int bd  = blockIdx.x;
    int tid = threadIdx.x;
    const float* x = g_rest + (size_t)bd * T_;

    for (int i = tid; i < 512; i += 256) {
        float s_, c_;
        sincosf(-6.28318530717958647692f * ((float)i * (1.f / 1024.f)), &s_, &c_);
        twi[i] = s_; twr[i] = c_;
    }
    for (int t = tid; t < 1024; t += 256) {
        int r = __brev((unsigned)t) >> 22;
        re[r] = x[t];
        im[r] = 0.f;
    }
    __syncthreads();

    for (int s = 1; s <= 10; s++) {
        int half = 1 << (s - 1);
        int shift = 10 - s;
        for (int j = tid; j < 512; j += 256) {
            int k  = j & (half - 1);
            int i0 = ((j >> (s - 1)) << s) + k;
            int i1 = i0 + half;
            int ti = k << shift;
            float wr_ = twr[ti], wi_ = twi[ti];
            float ar = re[i1], ai = im[i1];
            float tr = wr_ * ar - wi_ * ai;
            float tii = wr_ * ai + wi_ * ar;
            float br = re[i0], bi = im[i0];
            re[i0] = br + tr; im[i0] = bi + tii;
            re[i1] = br - tr; im[i1] = bi - tii;
        }
        __syncthreads();
    }

    for (int f = tid; f < 512; f += 256)
        mag[f] = (f == 0) ? -1.f : re[f] * re[f] + im[f] * im[f];
    __syncthreads();

    for (int kk = 0; kk < K_; kk++) {
        float best = -2.f; int bidx = 0;
        for (int f = tid; f < 512; f += 256) {
            float m = mag[f];
            if (m > best) { best = m; bidx = f; }
        }
        #pragma unroll
        for (int o = 16; o; o >>= 1) {
            float ob = __shfl_down_sync(0xffffffffu, best, o);
            int   oi = __shfl_down_sync(0xffffffffu, bidx, o);
            if (ob > best) { best = ob; bidx = oi; }
        }
        if ((tid & 31) == 0) { wbv[tid >> 5] = best; wbi[tid >> 5] = bidx; }
        __syncthreads();
        if (tid == 0) {
            for (int w = 1; w < 8; w++)
                if (wbv[w] > best) { best = wbv[w]; bidx = wbi[w]; }
            g_tkA[kk * (B_ * D_) + bd] = re[bidx] * (1.f / 512.f);
            g_tkB[kk * (B_ * D_) + bd] = im[bidx] * (1.f / 512.f);
            g_tki[kk * (B_ * D_) + bd] = bidx;
            mag[bidx] = -1.f;
        }
        __syncthreads();
    }
}

// ---------------------------------------------------------------------------
// Kernel 2: season synthesis via exact integer angle reduction + cos table.
//   season = sum_k A_k*ctab[(bidx*t)%1024] - B_k*stab[...]
//   Also: res1f = res - season (fp32), res1h = half(res1f)
// ---------------------------------------------------------------------------
__global__ __launch_bounds__(256) void season_k(const float* __restrict__ res,
                                                float* __restrict__ season_out) {
    __shared__ float sA[K_][256], sB[K_][256];
    __shared__ int   sI[K_][256];
    __shared__ float ctab[1024], stab[1024];
    int tid = threadIdx.x;
    int d   = blockIdx.x * 256 + tid;
    int b   = blockIdx.z;
    int bd  = b * D_ + d;
    for (int i = tid; i < 1024; i += 256) {
        float s_, c_;
        sincosf(6.28318530717958647692f * ((float)i * (1.f / 1024.f)), &s_, &c_);
        ctab[i] = c_; stab[i] = s_;
    }
    #pragma unroll
    for (int k = 0; k < K_; k++) {
        sA[k][tid] = g_tkA[k * (B_ * D_) + bd];
        sB[k][tid] = g_tkB[k * (B_ * D_) + bd];
        sI[k][tid] = g_tki[k * (B_ * D_) + bd];
    }
    __syncthreads();
    int t0 = blockIdx.y * 16;
    for (int tt = 0; tt < 16; tt++) {
        int t = t0 + tt;
        float sum = 0.f;
        #pragma unroll
        for (int k = 0; k < K_; k++) {
            int m = (sI[k][tid] * t) & 1023;
            sum += sA[k][tid] * ctab[m] - sB[k][tid] * stab[m];
        }
        season_out[((size_t)b * TP_ + t) * D_ + d] = sum;
        if (t < T_) {
            size_t ro = ((size_t)b * T_ + t) * D_ + d;
            float r1 = res[ro] - sum;
            g_res1f[ro] = r1;
            g_res1h[ro] = __float2half_rn(r1);
        }
    }
}

// ---------------------------------------------------------------------------
// Kernel 3: fp16 mma.sync GEMM (m16n8k16), ldmatrix, 4-stage cp.async.
//   CTA 128x128, 4 warps (2x2), warp tile 64x64, K-step 32.
//   C = A[M,K] @ BT[N,K]^T. epi: 0 -> Cf fp32; 1 -> gelu -> Ch half; 2 -> Cf + ADD
// ---------------------------------------------------------------------------
#define RP_ 80                     // bytes per 32-half row (pad 40 halves)
#define STAGE_B (256 * RP_)        // A(128 rows) + B(128 rows)
__global__ void __launch_bounds__(128, 2)
gemm_h(int M, int N, int K,
       const __half* __restrict__ A, const __half* __restrict__ BT,
       float* __restrict__ Cf, __half* __restrict__ Ch,
       int epi, const float* __restrict__ ADD) {
    extern __shared__ char smc[];
    uint32_t s0 = smem_u32(smc);
    int tid = threadIdx.x, wid = tid >> 5, lane = tid & 31;
    int wr = wid >> 1, wc = wid & 1;
    int g = lane >> 2, tg = lane & 3;
    int row0 = blockIdx.y * 128, col0 = blockIdx.x * 128;
    int lr = lane & 15, lcb = (lane >> 4) * 16;    // ldsm row-in-tile, col bytes

    float acc[4][8][4];
    #pragma unroll
    for (int i = 0; i < 4; i++)
        #pragma unroll
        for (int j = 0; j < 8; j++)
            #pragma unroll
            for (int q = 0; q < 4; q++) acc[i][j][q] = 0.f;

    const int S = K >> 5;
    auto issue = [&](int s) {
        int buf = s & 3;
        int k0 = s * 32;
        uint32_t da = s0 + buf * STAGE_B;
        uint32_t db = da + 128 * RP_;
        #pragma unroll
        for (int p = 0; p < 4; p++) {
            int c = tid + p * 128;
            int r = c >> 2, q = c & 3;
            cp16(da + r * RP_ + q * 16, A + (size_t)(row0 + r) * K + k0 + q * 8);
        }
        #pragma unroll
        for (int p = 0; p < 4; p++) {
            int c = tid + p * 128;
            int r = c >> 2, q = c & 3;
            cp16(db + r * RP_ + q * 16, BT + (size_t)(col0 + r) * K + k0 + q * 8);
        }
        CP_COMMIT();
    };

    issue(0);
    if (S > 1) issue(1);
    if (S > 2) issue(2);
    for (int s = 0; s < S; s++) {
        int buf = s & 3;
        if (s + 3 < S) {
            issue(s + 3);
            asm volatile("cp.async.wait_group 3;" ::: "memory");
        } else if (s + 2 < S) {
            asm volatile("cp.async.wait_group 2;" ::: "memory");
        } else if (s + 1 < S) {
            asm volatile("cp.async.wait_group 1;" ::: "memory");
        } else {
            asm volatile("cp.async.wait_group 0;" ::: "memory");
        }
        __syncthreads();
        uint32_t sa = s0 + buf * STAGE_B;
        uint32_t sb = sa + 128 * RP_;
        #pragma unroll
        for (int kh = 0; kh < 2; kh++) {
            uint32_t af[4][4], bf[8][2];
            #pragma unroll
            for (int mi = 0; mi < 4; mi++)
                ldsm4(af[mi], sa + (uint32_t)((wr * 64 + mi * 16 + lr) * RP_ + lcb + kh * 32));
            #pragma unroll
            for (int nt = 0; nt < 4; nt++) {
                uint32_t tb[4];
                ldsm4(tb, sb + (uint32_t)((wc * 64 + nt * 16 + lr) * RP_ + lcb + kh * 32));
                bf[nt * 2][0]     = tb[0]; bf[nt * 2][1]     = tb[2];
                bf[nt * 2 + 1][0] = tb[1]; bf[nt * 2 + 1][1] = tb[3];
            }
            #pragma unroll
            for (int mi = 0; mi < 4; mi++)
                #pragma unroll
                for (int ni = 0; ni < 8; ni++)
                    mma_f16(acc[mi][ni], af[mi], bf[ni]);
        }
        __syncthreads();
    }

    #pragma unroll
    for (int mi = 0; mi < 4; mi++) {
        #pragma unroll
        for (int hh = 0; hh < 2; hh++) {
            int r = row0 + wr * 64 + mi * 16 + g + hh * 8;
            if (r >= M) continue;
            #pragma unroll
            for (int ni = 0; ni < 8; ni++) {
                int c = col0 + wc * 64 + ni * 8 + tg * 2;
                float v0 = acc[mi][ni][hh * 2 + 0];
                float v1 = acc[mi][ni][hh * 2 + 1];
                if (epi == 1) {
                    v0 = 0.5f * v0 * (1.f + erff(v0 * 0.70710678118654752440f));
                    v1 = 0.5f * v1 * (1.f + erff(v1 * 0.70710678118654752440f));
                    *(__half2*)(Ch + (size_t)r * N + c) = __floats2half2_rn(v0, v1);
                } else {
                    if (epi == 2) {
                        const float* arow = ADD + (size_t)r * N;
                        v0 += arow[c]; v1 += arow[c + 1];
                    }
                    *(float2*)(Cf + (size_t)r * N + c) = make_float2(v0, v1);
                }
            }
        }
    }
}

// ---------------------------------------------------------------------------
// Kernel 4a: growth EMA partial scans -> g_gtmp (fp32), segment finals
// ---------------------------------------------------------------------------
__global__ __launch_bounds__(512) void growth_part(const float* __restrict__ z0,
        const float* __restrict__ sw) {
    int b = blockIdx.x, seg = blockIdx.y;
    int d = threadIdx.x;
    float w  = 1.f / (1.f + expf(-sw[d >> 6]));
    float om = 1.f - w;
    int t0 = seg * 64;
    const float* vp = g_v + ((size_t)b * T_ + t0) * D_ + d;
    float prev = (t0 == 0) ? z0[d] : vp[-(int)D_];
    float st = 0.f;
    float* gp = g_gtmp + ((size_t)b * T_ + t0) * D_ + d;
    #pragma unroll 8
    for (int t = 0; t < 64; t++) {
        float cur = vp[(size_t)t * D_];
        st = w * st + om * (cur - prev);
        prev = cur;
        gp[(size_t)t * D_] = st;
    }
    g_segf[((size_t)b * GSEG + seg) * D_ + d] = st;
}

// ---------------------------------------------------------------------------
// Kernel 4b: recombine + single rounding fp32 -> half into g_gpre
// ---------------------------------------------------------------------------
__global__ __launch_bounds__(512) void growth_apply(const float* __restrict__ sw,
        const float* __restrict__ v0) {
    int b = blockIdx.x, seg = blockIdx.y;
    int d = threadIdx.x;
    float w = 1.f / (1.f + expf(-sw[d >> 6]));
    float w2 = w * w, w4 = w2 * w2, w8 = w4 * w4, w16 = w8 * w8, w32 = w16 * w16;
    float wL = w32 * w32;
    float s_in = v0[d];
    for (int j = 0; j < seg; j++)
        s_in = wL * s_in + g_segf[((size_t)b * GSEG + j) * D_ + d];
    if (seg == 0)
        g_gpre[((size_t)b * T1_) * D_ + d] = __float2half_rn(v0[d]);
    const float* pp = g_gtmp + ((size_t)b * T_ + seg * 64) * D_ + d;
    __half* gp = g_gpre + ((size_t)b * T1_ + seg * 64 + 1) * D_ + d;
    float wp = w;
    #pragma unroll 8
    for (int t = 0; t < 64; t++) {
        gp[(size_t)t * D_] = __float2half_rn(pp[(size_t)t * D_] + wp * s_in);
        wp *= w;
    }
}

// ---------------------------------------------------------------------------
// Kernel 5: LayerNorm over D=512. If G: x = A - growth[b,t+1].
//   Writes fp32 out, optionally half copy (GEMM operand).
// ---------------------------------------------------------------------------
__global__ __launch_bounds__(128) void ln_k(const float* __restrict__ A,
        const float* __restrict__ G, const float* __restrict__ gam,
        const float* __restrict__ bet, float* __restrict__ outF,
        __half* __restrict__ outH) {
    __shared__ float sh[4], sh2[4];
    int row = blockIdx.x;
    int tid = threadIdx.x;
    const float* a = A + (size_t)row * D_;
    float x[4];
    if (G) {
        int b = row >> 10, t = row & 1023;
        const float* g = G + ((size_t)b * T1_ + t + 1) * D_;
        #pragma unroll
        for (int i = 0; i < 4; i++) x[i] = a[tid + i * 128] - g[tid + i * 128];
    } else {
        #pragma unroll
        for (int i = 0; i < 4; i++) x[i] = a[tid + i * 128];
    }
    float s = x[0] + x[1] + x[2] + x[3];
    #pragma unroll
    for (int o = 16; o; o >>= 1) s += __shfl_down_sync(0xffffffffu, s, o);
    if ((tid & 31) == 0) sh[tid >> 5] = s;
    __syncthreads();
    float mu = (sh[0] + sh[1] + sh[2] + sh[3]) * (1.f / 512.f);
    float vs = 0.f;
    #pragma unroll
    for (int i = 0; i < 4; i++) { float dx = x[i] - mu; vs += dx * dx; }
    #pragma unroll
    for (int o = 16; o; o >>= 1) vs += __shfl_down_sync(0xffffffffu, vs, o);
    if ((tid & 31) == 0) sh2[tid >> 5] = vs;
    __syncthreads();
    float var = (sh2[0] + sh2[1] + sh2[2] + sh2[3]) * (1.f / 512.f);
    float inv = rsqrtf(var + 1e-5f);
    float* oF = outF + (size_t)row * D_;
    __half* oH = outH ? outH + (size_t)row * D_ : nullptr;
    #pragma unroll
    for (int i = 0; i < 4; i++) {
        int c = tid + i * 128;
        float v = (x[i] - mu) * inv * gam[c] + bet[c];
        oF[c] = v;
        if (oH) oH[c] = __float2half_rn(v);
    }
}

// ---------------------------------------------------------------------------
// Kernel 6: fused skinny projections  (y=0: growth@gpw -> g_gg,
//                                      y=1: season@spw -> g_ss)
// ---------------------------------------------------------------------------
__global__ __launch_bounds__(256) void skinny2(const float* __restrict__ growth,
        const float* __restrict__ season, const float* __restrict__ gpw,
        const float* __restrict__ spw) {
    __shared__ float xs[512];
    int which = blockIdx.y;
    int r = blockIdx.x;
    int b = r >> 10, t = r & 1023;
    const float* X = which ? season + (size_t)b * TP_ * D_ + (size_t)t * D_
                           : growth + (size_t)b * T1_ * D_ + (size_t)t * D_;
    const float* W = which ? spw : gpw;
    float* out = which ? g_ss : g_gg;
    for (int i = threadIdx.x; i < 512; i += 256) xs[i] = X[i];
    __syncthreads();
    int w = threadIdx.x >> 5, lane = threadIdx.x & 31;
    if (w < CO_) {
        float s = 0.f;
        for (int i = lane; i < 512; i += 32) s += xs[i] * W[i * CO_ + w];
        #pragma unroll
        for (int o = 16; o; o >>= 1) s += __shfl_down_sync(0xffffffffu, s, o);
        if (!lane) out[(size_t)r * CO_ + w] = s;
    }
}

// ---------------------------------------------------------------------------
// Kernel 7: level EMA scan with aux growth term
// ---------------------------------------------------------------------------
__global__ __launch_bounds__(128) void level_scan(const float* __restrict__ level,
        const float* __restrict__ lsw, const float* __restrict__ lv0,
        float* __restrict__ out) {
    int idx = threadIdx.x;
    if (idx >= B_ * CO_) return;
    int b = idx / CO_, c = idx % CO_;
    float w  = 1.f / (1.f + expf(-lsw[c]));
    float om = 1.f - w;
    float state = lv0[c];
    const float* lp = level + (size_t)b * T_ * CO_ + c;
    const float* sp = g_ss  + (size_t)b * T_ * CO_ + c;
    const float* gp = g_gg  + (size_t)b * T_ * CO_ + c;
    float*       op = out   + (size_t)b * T_ * CO_ + c;
    #pragma unroll 4
    for (int t = 0; t < T_; t++) {
        float val = lp[t * CO_] - sp[t * CO_];
        state = w * state + om * val + w * gp[t * CO_];
        op[t * CO_] = state;
    }
}

// ---------------------------------------------------------------------------
// Launch
// ---------------------------------------------------------------------------
extern "C" void kernel_launch(void* const* d_in, const int* in_sizes, int n_in,
                              void* d_out, int out_size) {
    const float* res  = (const float*)d_in[0];
    const float* lvl  = (const float*)d_in[1];
    const float* inw  = (const float*)d_in[2];
    const float* outw = (const float*)d_in[3];
    const float* z0   = (const float*)d_in[4];
    const float* gsw  = (const float*)d_in[5];
    const float* gv0  = (const float*)d_in[6];
    const float* ffw1 = (const float*)d_in[7];
    const float* ffw2 = (const float*)d_in[8];
    const float* n1g  = (const float*)d_in[9];
    const float* n1b  = (const float*)d_in[10];
    const float* n2g  = (const float*)d_in[11];
    const float* n2b  = (const float*)d_in[12];
    const float* gpw  = (const float*)d_in[13];
    const float* spw  = (const float*)d_in[14];
    const float* lsw  = (const float*)d_in[15];
    const float* lv0  = (const float*)d_in[16];

    float* out        = (float*)d_out;
    float* out_res3   = out;
    float* out_level  = out_res3  + (size_t)B_ * T_ * D_;
    float* out_growth = out_level + (size_t)B_ * T_ * CO_;
    float* out_season = out_growth + (size_t)B_ * T1_ * D_;

    float *p_res1f, *p_v, *p_res2f, *p_pre;
    __half *p_res1h, *p_gpre, *p_res2h, *p_hid;
    __half *p_win, *p_wout, *p_wf1, *p_wf2;
    cudaGetSymbolAddress((void**)&p_res1f, g_res1f);
    cudaGetSymbolAddress((void**)&p_res1h, g_res1h);
    cudaGetSymbolAddress((void**)&p_v,     g_v);
    cudaGetSymbolAddress((void**)&p_gpre,  g_gpre);
    cudaGetSymbolAddress((void**)&p_res2f, g_res2f);
    cudaGetSymbolAddress((void**)&p_res2h, g_res2h);
    cudaGetSymbolAddress((void**)&p_hid,   g_hid);
    cudaGetSymbolAddress((void**)&p_pre,   g_pre);
    cudaGetSymbolAddress((void**)&p_win,   g_win);
    cudaGetSymbolAddress((void**)&p_wout,  g_wout);
    cudaGetSymbolAddress((void**)&p_wf1,   g_wf1);
    cudaGetSymbolAddress((void**)&p_wf2,   g_wf2);

    const int GSMEM = 4 * STAGE_B;   // 81920 bytes
    static int smem_set = 0;
    if (!smem_set) {
        cudaFuncSetAttribute(gemm_h, cudaFuncAttributeMaxDynamicSharedMemorySize, GSMEM);
        smem_set = 1;
    }

    // 0. weight transposes (fp16), res transpose for FFT
    transpose_h<<<dim3(D_ / 32, D_ / 32), 256>>>(inw,  p_win,  D_, D_);
    transpose_h<<<dim3(D_ / 32, D_ / 32), 256>>>(outw, p_wout, D_, D_);
    transpose_h<<<dim3(LAT_ / 32, D_ / 32), 256>>>(ffw1, p_wf1, D_, LAT_);
    transpose_h<<<dim3(D_ / 32, LAT_ / 32), 256>>>(ffw2, p_wf2, LAT_, D_);
    transpose_res<<<dim3(D_ / 32, T_ / 32, B_), 256>>>(res);
    // 1. FFT + top-k
    fft_topk<<<B_ * D_, 256>>>();
    // 2. season (table synthesis) + res1
    season_k<<<dim3(D_ / 256, TP_ / 16, B_), 256>>>(res, out_season);
    // 3. v = res1 @ in_w  (fp16 tensor)
    gemm_h<<<dim3(D_ / 128, (B_ * T_) / 128), 128, GSMEM>>>(
        B_ * T_, D_, D_, p_res1h, p_win, p_v, nullptr, 0, nullptr);
    // 4. growth EMA: segmented scan (fp32 partials, single half rounding)
    growth_part<<<dim3(B_, GSEG), 512>>>(z0, gsw);
    growth_apply<<<dim3(B_, GSEG), 512>>>(gsw, gv0);
    // 5. growth = gpre @ out_w -> output (fp32)
    gemm_h<<<dim3(D_ / 128, (B_ * T1_ + 127) / 128), 128, GSMEM>>>(
        B_ * T1_, D_, D_, p_gpre, p_wout, out_growth, nullptr, 0, nullptr);
    // 6. res2 = LN1(res1 - growth[:,1:])
    ln_k<<<B_ * T_, 128>>>(p_res1f, out_growth, n1g, n1b, p_res2f, p_res2h);
    // 7. hid = gelu(res2 @ ff_w1) -> half
    gemm_h<<<dim3(LAT_ / 128, (B_ * T_) / 128), 128, GSMEM>>>(
        B_ * T_, LAT_, D_, p_res2h, p_wf1, nullptr, p_hid, 1, nullptr);
    // 8. pre = hid @ ff_w2 + res2
    gemm_h<<<dim3(D_ / 128, (B_ * T_) / 128), 128, GSMEM>>>(
        B_ * T_, D_, LAT_, p_hid, p_wf2, p_pre, nullptr, 2, p_res2f);
    // 9. res3 = LN2(pre) -> output
    ln_k<<<B_ * T_, 128>>>(p_pre, nullptr, n2g, n2b, out_res3, nullptr);
    // 10. fused skinny projections
    skinny2<<<dim3(B_ * T_, 2), 256>>>(out_growth, out_season, gpw, spw);
    // 11. level EMA scan -> output
    level_scan<<<1, 128>>>(lvl, lsw, lv0, out_level);
}

// round 12
// speedup vs baseline: 3.1753x; 1.0207x over previous
#include <cuda_runtime.h>
#include <cuda_fp16.h>
#include <math.h>
#include <stdint.h>

// ---------------------------------------------------------------------------
// Problem constants
// ---------------------------------------------------------------------------
#define B_   16
#define T_   1024
#define D_   512
#define CO_  7
#define PRED_ 96
#define K_   8
#define LAT_ 2048
#define TP_  (T_ + PRED_)   // 1120
#define T1_  (T_ + 1)       // 1025
#define GSEG 16             // growth scan segments (64 steps each)
#define MPAD_G 16512        // 129*128 padded rows for growth GEMM

// ---------------------------------------------------------------------------
// Static device scratch
// ---------------------------------------------------------------------------
__device__ float  g_res1f[(size_t)B_ * T_ * D_];
__device__ __half g_res1h[(size_t)B_ * T_ * D_];
__device__ float  g_rest [(size_t)B_ * D_ * T_];        // res transposed [b][d][t]
__device__ float  g_v    [(size_t)B_ * T_ * D_];
__device__ float  g_gtmp [(size_t)B_ * T_ * D_];        // growth partial states (fp32)
__device__ __half g_gpre [(size_t)MPAD_G * D_];         // half GEMM input (pad = 0)
__device__ float  g_res2f[(size_t)B_ * T_ * D_];
__device__ __half g_res2h[(size_t)B_ * T_ * D_];
__device__ __half g_hid  [(size_t)B_ * T_ * LAT_];
__device__ float  g_pre  [(size_t)B_ * T_ * D_];
__device__ float  g_gg   [(size_t)B_ * T_ * CO_];
__device__ float  g_ss   [(size_t)B_ * T_ * CO_];
__device__ float  g_tkA  [K_ * B_ * D_];                // re/512
__device__ float  g_tkB  [K_ * B_ * D_];                // im/512
__device__ int    g_tki  [K_ * B_ * D_];                // freq bin index
__device__ float  g_segf [(size_t)B_ * GSEG * D_];
__device__ float2 g_trig [1024];                        // e^{+i 2pi j/1024}
// transposed + fp16-rounded weights [N][K]
__device__ __half g_win [(size_t)D_ * D_];
__device__ __half g_wout[(size_t)D_ * D_];
__device__ __half g_wf1 [(size_t)LAT_ * D_];
__device__ __half g_wf2 [(size_t)D_ * LAT_];

// ---------------------------------------------------------------------------
// Helpers
// ---------------------------------------------------------------------------
__device__ __forceinline__ uint32_t smem_u32(const void* p) {
    uint32_t a;
    asm("{ .reg .u64 t; cvta.to.shared.u64 t, %1; cvt.u32.u64 %0, t; }" : "=r"(a) : "l"(p));
    return a;
}
__device__ __forceinline__ void cp16(uint32_t dst, const void* src) {
    asm volatile("cp.async.cg.shared.global [%0], [%1], 16;" :: "r"(dst), "l"(src));
}
#define CP_COMMIT() asm volatile("cp.async.commit_group;" ::: "memory")

__device__ __forceinline__ void mma_f16(float* c, const uint32_t* a, const uint32_t* b) {
    asm volatile(
        "mma.sync.aligned.m16n8k16.row.col.f32.f16.f16.f32 "
        "{%0,%1,%2,%3}, {%4,%5,%6,%7}, {%8,%9}, {%0,%1,%2,%3};"
        : "+f"(c[0]), "+f"(c[1]), "+f"(c[2]), "+f"(c[3])
        : "r"(a[0]), "r"(a[1]), "r"(a[2]), "r"(a[3]), "r"(b[0]), "r"(b[1]));
}
__device__ __forceinline__ void ldsm4(uint32_t* r, uint32_t addr) {
    asm volatile("ldmatrix.sync.aligned.m8n8.x4.shared.b16 {%0,%1,%2,%3}, [%4];"
        : "=r"(r[0]), "=r"(r[1]), "=r"(r[2]), "=r"(r[3]) : "r"(addr));
}

// ---------------------------------------------------------------------------
// Kernel: trig table  g_trig[j] = (cos, sin)(2 pi j / 1024)
// ---------------------------------------------------------------------------
__global__ void trig_init() {
    int i = threadIdx.x;
    float s_, c_;
    sincosf(6.28318530717958647692f * ((float)i * (1.f / 1024.f)), &s_, &c_);
    g_trig[i] = make_float2(c_, s_);
}

// ---------------------------------------------------------------------------
// Kernel: weight transpose [K,N] -> [N,K], rounded fp32 -> fp16
// ---------------------------------------------------------------------------
__global__ __launch_bounds__(256) void transpose_h(const float* __restrict__ W,
        __half* __restrict__ WT, int K, int N) {
    __shared__ float t[32][33];
    int n0 = blockIdx.x * 32, k0 = blockIdx.y * 32;
    int tx = threadIdx.x & 31, ty = threadIdx.x >> 5;   // 32x8
    #pragma unroll
    for (int i = 0; i < 32; i += 8)
        t[ty + i][tx] = W[(size_t)(k0 + ty + i) * N + n0 + tx];
    __syncthreads();
    #pragma unroll
    for (int i = 0; i < 32; i += 8)
        WT[(size_t)(n0 + ty + i) * K + k0 + tx] = __float2half_rn(t[tx][ty + i]);
}

// ---------------------------------------------------------------------------
// Kernel: res transpose [b][t][d] -> [b][d][t] (coalesced FFT input)
// ---------------------------------------------------------------------------
__global__ __launch_bounds__(256) void transpose_res(const float* __restrict__ X) {
    __shared__ float t[32][33];
    int d0 = blockIdx.x * 32, t0 = blockIdx.y * 32, b = blockIdx.z;
    int tx = threadIdx.x & 31, ty = threadIdx.x >> 5;
    #pragma unroll
    for (int i = 0; i < 32; i += 8)
        t[ty + i][tx] = X[((size_t)b * T_ + t0 + ty + i) * D_ + d0 + tx];
    __syncthreads();
    #pragma unroll
    for (int i = 0; i < 32; i += 8)
        g_rest[((size_t)b * D_ + d0 + ty + i) * T_ + t0 + tx] = t[tx][ty + i];
}

// ---------------------------------------------------------------------------
// Kernel 1: per-(b,d) 1024-pt radix-2 FFT + top-8 selection (256 threads)
// ---------------------------------------------------------------------------
__global__ __launch_bounds__(256) void fft_topk() {
    __shared__ float re[1024], im[1024], mag[512];
    __shared__ float twr[512], twi[512];
    __shared__ float wbv[8];
    __shared__ int   wbi[8];
    int bd  = blockIdx.x;
    int tid = threadIdx.x;
    const float* x = g_rest + (size_t)bd * T_;

    // forward twiddles = conj(g_trig): cos, -sin  (bit-identical to sincosf(-x))
    for (int i = tid; i < 512; i += 256) {
        float2 t = g_trig[i];
        twr[i] = t.x; twi[i] = -t.y;
    }
    for (int t = tid; t < 1024; t += 256) {
        int r = __brev((unsigned)t) >> 22;
        re[r] = x[t];
        im[r] = 0.f;
    }
    __syncthreads();

    for (int s = 1; s <= 10; s++) {
        int half = 1 << (s - 1);
        int shift = 10 - s;
        for (int j = tid; j < 512; j += 256) {
            int k  = j & (half - 1);
            int i0 = ((j >> (s - 1)) << s) + k;
            int i1 = i0 + half;
            int ti = k << shift;
            float wr_ = twr[ti], wi_ = twi[ti];
            float ar = re[i1], ai = im[i1];
            float tr = wr_ * ar - wi_ * ai;
            float tii = wr_ * ai + wi_ * ar;
            float br = re[i0], bi = im[i0];
            re[i0] = br + tr; im[i0] = bi + tii;
            re[i1] = br - tr; im[i1] = bi - tii;
        }
        __syncthreads();
    }

    for (int f = tid; f < 512; f += 256)
        mag[f] = (f == 0) ? -1.f : re[f] * re[f] + im[f] * im[f];
    __syncthreads();

    for (int kk = 0; kk < K_; kk++) {
        float best = -2.f; int bidx = 0;
        for (int f = tid; f < 512; f += 256) {
            float m = mag[f];
            if (m > best) { best = m; bidx = f; }
        }
        #pragma unroll
        for (int o = 16; o; o >>= 1) {
            float ob = __shfl_down_sync(0xffffffffu, best, o);
            int   oi = __shfl_down_sync(0xffffffffu, bidx, o);
            if (ob > best) { best = ob; bidx = oi; }
        }
        if ((tid & 31) == 0) { wbv[tid >> 5] = best; wbi[tid >> 5] = bidx; }
        __syncthreads();
        if (tid == 0) {
            for (int w = 1; w < 8; w++)
                if (wbv[w] > best) { best = wbv[w]; bidx = wbi[w]; }
            g_tkA[kk * (B_ * D_) + bd] = re[bidx] * (1.f / 512.f);
            g_tkB[kk * (B_ * D_) + bd] = im[bidx] * (1.f / 512.f);
            g_tki[kk * (B_ * D_) + bd] = bidx;
            mag[bidx] = -1.f;
        }
        __syncthreads();
    }
}

// ---------------------------------------------------------------------------
// Kernel 2: season synthesis (exact integer angle reduction + float2 table)
// ---------------------------------------------------------------------------
__global__ __launch_bounds__(256) void season_k(const float* __restrict__ res,
                                                float* __restrict__ season_out) {
    __shared__ float sA[K_][256], sB[K_][256];
    __shared__ int   sI[K_][256];
    __shared__ float2 tt[1024];
    int tid = threadIdx.x;
    int d   = blockIdx.x * 256 + tid;
    int b   = blockIdx.z;
    int bd  = b * D_ + d;
    for (int i = tid; i < 1024; i += 256) tt[i] = g_trig[i];
    #pragma unroll
    for (int k = 0; k < K_; k++) {
        sA[k][tid] = g_tkA[k * (B_ * D_) + bd];
        sB[k][tid] = g_tkB[k * (B_ * D_) + bd];
        sI[k][tid] = g_tki[k * (B_ * D_) + bd];
    }
    __syncthreads();
    int t0 = blockIdx.y * 16;
    for (int tt_i = 0; tt_i < 16; tt_i++) {
        int t = t0 + tt_i;
        float sum = 0.f;
        #pragma unroll
        for (int k = 0; k < K_; k++) {
            int m = (sI[k][tid] * t) & 1023;
            float2 cs = tt[m];
            sum += sA[k][tid] * cs.x - sB[k][tid] * cs.y;
        }
        season_out[((size_t)b * TP_ + t) * D_ + d] = sum;
        if (t < T_) {
            size_t ro = ((size_t)b * T_ + t) * D_ + d;
            float r1 = res[ro] - sum;
            g_res1f[ro] = r1;
            g_res1h[ro] = __float2half_rn(r1);
        }
    }
}

// ---------------------------------------------------------------------------
// Kernel 3: fp16 mma.sync GEMM (m16n8k16), ldmatrix, 4-stage cp.async.
//   CTA 128x128, 8 warps (4 row x 2 col), warp tile 32x64, K-step 32.
//   C = A[M,K] @ BT[N,K]^T. epi: 0 -> Cf fp32; 1 -> gelu -> Ch half; 2 -> Cf + ADD
// ---------------------------------------------------------------------------
#define RP_ 80                     // bytes per 32-half row (pad 40 halves)
#define STAGE_B (256 * RP_)        // A(128 rows) + B(128 rows)
__global__ void __launch_bounds__(256, 2)
gemm_h(int M, int N, int K,
       const __half* __restrict__ A, const __half* __restrict__ BT,
       float* __restrict__ Cf, __half* __restrict__ Ch,
       int epi, const float* __restrict__ ADD) {
    extern __shared__ char smc[];
    uint32_t s0 = smem_u32(smc);
    int tid = threadIdx.x, wid = tid >> 5, lane = tid & 31;
    int wr = wid >> 1, wc = wid & 1;            // 4 row-warps x 2 col-warps
    int g = lane >> 2, tg = lane & 3;
    int row0 = blockIdx.y * 128, col0 = blockIdx.x * 128;
    int lr = lane & 15, lcb = (lane >> 4) * 16;

    float acc[2][8][4];
    #pragma unroll
    for (int i = 0; i < 2; i++)
        #pragma unroll
        for (int j = 0; j < 8; j++)
            #pragma unroll
            for (int q = 0; q < 4; q++) acc[i][j][q] = 0.f;

    const int S = K >> 5;
    auto issue = [&](int s) {
        int buf = s & 3;
        int k0 = s * 32;
        uint32_t da = s0 + buf * STAGE_B;
        uint32_t db = da + 128 * RP_;
        #pragma unroll
        for (int p = 0; p < 2; p++) {
            int c = tid + p * 256;
            int r = c >> 2, q = c & 3;
            cp16(da + r * RP_ + q * 16, A + (size_t)(row0 + r) * K + k0 + q * 8);
        }
        #pragma unroll
        for (int p = 0; p < 2; p++) {
            int c = tid + p * 256;
            int r = c >> 2, q = c & 3;
            cp16(db + r * RP_ + q * 16, BT + (size_t)(col0 + r) * K + k0 + q * 8);
        }
        CP_COMMIT();
    };

    issue(0);
    if (S > 1) issue(1);
    if (S > 2) issue(2);
    for (int s = 0; s < S; s++) {
        int buf = s & 3;
        if (s + 3 < S) {
            issue(s + 3);
            asm volatile("cp.async.wait_group 3;" ::: "memory");
        } else if (s + 2 < S) {
            asm volatile("cp.async.wait_group 2;" ::: "memory");
        } else if (s + 1 < S) {
            asm volatile("cp.async.wait_group 1;" ::: "memory");
        } else {
            asm volatile("cp.async.wait_group 0;" ::: "memory");
        }
        __syncthreads();
        uint32_t sa = s0 + buf * STAGE_B;
        uint32_t sb = sa + 128 * RP_;
        #pragma unroll
        for (int kh = 0; kh < 2; kh++) {
            uint32_t af[2][4], bf[8][2];
            #pragma unroll
            for (int mi = 0; mi < 2; mi++)
                ldsm4(af[mi], sa + (uint32_t)((wr * 32 + mi * 16 + lr) * RP_ + lcb + kh * 32));
            #pragma unroll
            for (int nt = 0; nt < 4; nt++) {
                uint32_t tb[4];
                ldsm4(tb, sb + (uint32_t)((wc * 64 + nt * 16 + lr) * RP_ + lcb + kh * 32));
                bf[nt * 2][0]     = tb[0]; bf[nt * 2][1]     = tb[2];
                bf[nt * 2 + 1][0] = tb[1]; bf[nt * 2 + 1][1] = tb[3];
            }
            #pragma unroll
            for (int mi = 0; mi < 2; mi++)
                #pragma unroll
                for (int ni = 0; ni < 8; ni++)
                    mma_f16(acc[mi][ni], af[mi], bf[ni]);
        }
        __syncthreads();
    }

    #pragma unroll
    for (int mi = 0; mi < 2; mi++) {
        #pragma unroll
        for (int hh = 0; hh < 2; hh++) {
            int r = row0 + wr * 32 + mi * 16 + g + hh * 8;
            if (r >= M) continue;
            #pragma unroll
            for (int ni = 0; ni < 8; ni++) {
                int c = col0 + wc * 64 + ni * 8 + tg * 2;
                float v0 = acc[mi][ni][hh * 2 + 0];
                float v1 = acc[mi][ni][hh * 2 + 1];
                if (epi == 1) {
                    v0 = 0.5f * v0 * (1.f + erff(v0 * 0.70710678118654752440f));
                    v1 = 0.5f * v1 * (1.f + erff(v1 * 0.70710678118654752440f));
                    *(__half2*)(Ch + (size_t)r * N + c) = __floats2half2_rn(v0, v1);
                } else {
                    if (epi == 2) {
                        const float* arow = ADD + (size_t)r * N;
                        v0 += arow[c]; v1 += arow[c + 1];
                    }
                    *(float2*)(Cf + (size_t)r * N + c) = make_float2(v0, v1);
                }
            }
        }
    }
}

// ---------------------------------------------------------------------------
// Kernel 4a: growth EMA partial scans -> g_gtmp (fp32), segment finals
// ---------------------------------------------------------------------------
__global__ __launch_bounds__(512) void growth_part(const float* __restrict__ z0,
        const float* __restrict__ sw) {
    int b = blockIdx.x, seg = blockIdx.y;
    int d = threadIdx.x;
    float w  = 1.f / (1.f + expf(-sw[d >> 6]));
    float om = 1.f - w;
    int t0 = seg * 64;
    const float* vp = g_v + ((size_t)b * T_ + t0) * D_ + d;
    float prev = (t0 == 0) ? z0[d] : vp[-(int)D_];
    float st = 0.f;
    float* gp = g_gtmp + ((size_t)b * T_ + t0) * D_ + d;
    #pragma unroll 8
    for (int t = 0; t < 64; t++) {
        float cur = vp[(size_t)t * D_];
        st = w * st + om * (cur - prev);
        prev = cur;
        gp[(size_t)t * D_] = st;
    }
    g_segf[((size_t)b * GSEG + seg) * D_ + d] = st;
}

// ---------------------------------------------------------------------------
// Kernel 4b: recombine + single rounding fp32 -> half into g_gpre
// ---------------------------------------------------------------------------
__global__ __launch_bounds__(512) void growth_apply(const float* __restrict__ sw,
        const float* __restrict__ v0) {
    int b = blockIdx.x, seg = blockIdx.y;
    int d = threadIdx.x;
    float w = 1.f / (1.f + expf(-sw[d >> 6]));
    float w2 = w * w, w4 = w2 * w2, w8 = w4 * w4, w16 = w8 * w8, w32 = w16 * w16;
    float wL = w32 * w32;
    float s_in = v0[d];
    for (int j = 0; j < seg; j++)
        s_in = wL * s_in + g_segf[((size_t)b * GSEG + j) * D_ + d];
    if (seg == 0)
        g_gpre[((size_t)b * T1_) * D_ + d] = __float2half_rn(v0[d]);
    const float* pp = g_gtmp + ((size_t)b * T_ + seg * 64) * D_ + d;
    __half* gp = g_gpre + ((size_t)b * T1_ + seg * 64 + 1) * D_ + d;
    float wp = w;
    #pragma unroll 8
    for (int t = 0; t < 64; t++) {
        gp[(size_t)t * D_] = __float2half_rn(pp[(size_t)t * D_] + wp * s_in);
        wp *= w;
    }
}

// ---------------------------------------------------------------------------
// Kernel 5: LayerNorm over D=512. If G: x = A - growth[b,t+1].
// ---------------------------------------------------------------------------
__global__ __launch_bounds__(128) void ln_k(const float* __restrict__ A,
        const float* __restrict__ G, const float* __restrict__ gam,
        const float* __restrict__ bet, float* __restrict__ outF,
        __half* __restrict__ outH) {
    __shared__ float sh[4], sh2[4];
    int row = blockIdx.x;
    int tid = threadIdx.x;
    const float* a = A + (size_t)row * D_;
    float x[4];
    if (G) {
        int b = row >> 10, t = row & 1023;
        const float* g = G + ((size_t)b * T1_ + t + 1) * D_;
        #pragma unroll
        for (int i = 0; i < 4; i++) x[i] = a[tid + i * 128] - g[tid + i * 128];
    } else {
        #pragma unroll
        for (int i = 0; i < 4; i++) x[i] = a[tid + i * 128];
    }
    float s = x[0] + x[1] + x[2] + x[3];
    #pragma unroll
    for (int o = 16; o; o >>= 1) s += __shfl_down_sync(0xffffffffu, s, o);
    if ((tid & 31) == 0) sh[tid >> 5] = s;
    __syncthreads();
    float mu = (sh[0] + sh[1] + sh[2] + sh[3]) * (1.f / 512.f);
    float vs = 0.f;
    #pragma unroll
    for (int i = 0; i < 4; i++) { float dx = x[i] - mu; vs += dx * dx; }
    #pragma unroll
    for (int o = 16; o; o >>= 1) vs += __shfl_down_sync(0xffffffffu, vs, o);
    if ((tid & 31) == 0) sh2[tid >> 5] = vs;
    __syncthreads();
    float var = (sh2[0] + sh2[1] + sh2[2] + sh2[3]) * (1.f / 512.f);
    float inv = rsqrtf(var + 1e-5f);
    float* oF = outF + (size_t)row * D_;
    __half* oH = outH ? outH + (size_t)row * D_ : nullptr;
    #pragma unroll
    for (int i = 0; i < 4; i++) {
        int c = tid + i * 128;
        float v = (x[i] - mu) * inv * gam[c] + bet[c];
        oF[c] = v;
        if (oH) oH[c] = __float2half_rn(v);
    }
}

// ---------------------------------------------------------------------------
// Kernel 6: fused skinny projections
// ---------------------------------------------------------------------------
__global__ __launch_bounds__(256) void skinny2(const float* __restrict__ growth,
        const float* __restrict__ season, const float* __restrict__ gpw,
        const float* __restrict__ spw) {
    __shared__ float xs[512];
    int which = blockIdx.y;
    int r = blockIdx.x;
    int b = r >> 10, t = r & 1023;
    const float* X = which ? season + (size_t)b * TP_ * D_ + (size_t)t * D_
                           : growth + (size_t)b * T1_ * D_ + (size_t)t * D_;
    const float* W = which ? spw : gpw;
    float* out = which ? g_ss : g_gg;
    for (int i = threadIdx.x; i < 512; i += 256) xs[i] = X[i];
    __syncthreads();
    int w = threadIdx.x >> 5, lane = threadIdx.x & 31;
    if (w < CO_) {
        float s = 0.f;
        for (int i = lane; i < 512; i += 32) s += xs[i] * W[i * CO_ + w];
        #pragma unroll
        for (int o = 16; o; o >>= 1) s += __shfl_down_sync(0xffffffffu, s, o);
        if (!lane) out[(size_t)r * CO_ + w] = s;
    }
}

// ---------------------------------------------------------------------------
// Kernel 7: level EMA scan with aux growth term
// ---------------------------------------------------------------------------
__global__ __launch_bounds__(128) void level_scan(const float* __restrict__ level,
        const float* __restrict__ lsw, const float* __restrict__ lv0,
        float* __restrict__ out) {
    int idx = threadIdx.x;
    if (idx >= B_ * CO_) return;
    int b = idx / CO_, c = idx % CO_;
    float w  = 1.f / (1.f + expf(-lsw[c]));
    float om = 1.f - w;
    float state = lv0[c];
    const float* lp = level + (size_t)b * T_ * CO_ + c;
    const float* sp = g_ss  + (size_t)b * T_ * CO_ + c;
    const float* gp = g_gg  + (size_t)b * T_ * CO_ + c;
    float*       op = out   + (size_t)b * T_ * CO_ + c;
    #pragma unroll 4
    for (int t = 0; t < T_; t++) {
        float val = lp[t * CO_] - sp[t * CO_];
        state = w * state + om * val + w * gp[t * CO_];
        op[t * CO_] = state;
    }
}

// ---------------------------------------------------------------------------
// Launch
// ---------------------------------------------------------------------------
extern "C" void kernel_launch(void* const* d_in, const int* in_sizes, int n_in,
                              void* d_out, int out_size) {
    const float* res  = (const float*)d_in[0];
    const float* lvl  = (const float*)d_in[1];
    const float* inw  = (const float*)d_in[2];
    const float* outw = (const float*)d_in[3];
    const float* z0   = (const float*)d_in[4];
    const float* gsw  = (const float*)d_in[5];
    const float* gv0  = (const float*)d_in[6];
    const float* ffw1 = (const float*)d_in[7];
    const float* ffw2 = (const float*)d_in[8];
    const float* n1g  = (const float*)d_in[9];
    const float* n1b  = (const float*)d_in[10];
    const float* n2g  = (const float*)d_in[11];
    const float* n2b  = (const float*)d_in[12];
    const float* gpw  = (const float*)d_in[13];
    const float* spw  = (const float*)d_in[14];
    const float* lsw  = (const float*)d_in[15];
    const float* lv0  = (const float*)d_in[16];

    float* out        = (float*)d_out;
    float* out_res3   = out;
    float* out_level  = out_res3  + (size_t)B_ * T_ * D_;
    float* out_growth = out_level + (size_t)B_ * T_ * CO_;
    float* out_season = out_growth + (size_t)B_ * T1_ * D_;

    float *p_res1f, *p_v, *p_res2f, *p_pre;
    __half *p_res1h, *p_gpre, *p_res2h, *p_hid;
    __half *p_win, *p_wout, *p_wf1, *p_wf2;
    cudaGetSymbolAddress((void**)&p_res1f, g_res1f);
    cudaGetSymbolAddress((void**)&p_res1h, g_res1h);
    cudaGetSymbolAddress((void**)&p_v,     g_v);
    cudaGetSymbolAddress((void**)&p_gpre,  g_gpre);
    cudaGetSymbolAddress((void**)&p_res2f, g_res2f);
    cudaGetSymbolAddress((void**)&p_res2h, g_res2h);
    cudaGetSymbolAddress((void**)&p_hid,   g_hid);
    cudaGetSymbolAddress((void**)&p_pre,   g_pre);
    cudaGetSymbolAddress((void**)&p_win,   g_win);
    cudaGetSymbolAddress((void**)&p_wout,  g_wout);
    cudaGetSymbolAddress((void**)&p_wf1,   g_wf1);
    cudaGetSymbolAddress((void**)&p_wf2,   g_wf2);

    const int GSMEM = 4 * STAGE_B;   // 81920 bytes
    static int smem_set = 0;
    if (!smem_set) {
        cudaFuncSetAttribute(gemm_h, cudaFuncAttributeMaxDynamicSharedMemorySize, GSMEM);
        smem_set = 1;
    }

    // 0. weight transposes (fp16), res transpose, trig table
    transpose_h<<<dim3(D_ / 32, D_ / 32), 256>>>(inw,  p_win,  D_, D_);
    transpose_h<<<dim3(D_ / 32, D_ / 32), 256>>>(outw, p_wout, D_, D_);
    transpose_h<<<dim3(LAT_ / 32, D_ / 32), 256>>>(ffw1, p_wf1, D_, LAT_);
    transpose_h<<<dim3(D_ / 32, LAT_ / 32), 256>>>(ffw2, p_wf2, LAT_, D_);
    transpose_res<<<dim3(D_ / 32, T_ / 32, B_), 256>>>(res);
    trig_init<<<1, 1024>>>();
    // 1. FFT + top-k
    fft_topk<<<B_ * D_, 256>>>();
    // 2. season + res1
    season_k<<<dim3(D_ / 256, TP_ / 16, B_), 256>>>(res, out_season);
    // 3. v = res1 @ in_w
    gemm_h<<<dim3(D_ / 128, (B_ * T_) / 128), 256, GSMEM>>>(
        B_ * T_, D_, D_, p_res1h, p_win, p_v, nullptr, 0, nullptr);
    // 4. growth EMA segmented scan
    growth_part<<<dim3(B_, GSEG), 512>>>(z0, gsw);
    growth_apply<<<dim3(B_, GSEG), 512>>>(gsw, gv0);
    // 5. growth = gpre @ out_w
    gemm_h<<<dim3(D_ / 128, (B_ * T1_ + 127) / 128), 256, GSMEM>>>(
        B_ * T1_, D_, D_, p_gpre, p_wout, out_growth, nullptr, 0, nullptr);
    // 6. res2 = LN1(res1 - growth[:,1:])
    ln_k<<<B_ * T_, 128>>>(p_res1f, out_growth, n1g, n1b, p_res2f, p_res2h);
    // 7. hid = gelu(res2 @ ff_w1) -> half
    gemm_h<<<dim3(LAT_ / 128, (B_ * T_) / 128), 256, GSMEM>>>(
        B_ * T_, LAT_, D_, p_res2h, p_wf1, nullptr, p_hid, 1, nullptr);
    // 8. pre = hid @ ff_w2 + res2
    gemm_h<<<dim3(D_ / 128, (B_ * T_) / 128), 256, GSMEM>>>(
        B_ * T_, D_, LAT_, p_hid, p_wf2, p_pre, nullptr, 2, p_res2f);
    // 9. res3 = LN2(pre)
    ln_k<<<B_ * T_, 128>>>(p_pre, nullptr, n2g, n2b, out_res3, nullptr);
    // 10. skinny projections
    skinny2<<<dim3(B_ * T_, 2), 256>>>(out_growth, out_season, gpw, spw);
    // 11. level EMA scan
    level_scan<<<1, 128>>>(lvl, lsw, lv0, out_level);
}

// round 13
// speedup vs baseline: 3.8166x; 1.2020x over previous
#include <cuda_runtime.h>
#include <cuda_fp16.h>
#include <math.h>
#include <stdint.h>

// ---------------------------------------------------------------------------
// Problem constants
// ---------------------------------------------------------------------------
#define B_   16
#define T_   1024
#define D_   512
#define CO_  7
#define PRED_ 96
#define K_   8
#define LAT_ 2048
#define TP_  (T_ + PRED_)   // 1120
#define T1_  (T_ + 1)       // 1025
#define GSEG 16             // growth scan segments (64 steps each)
#define LSEG 16             // level scan segments (64 steps each)
#define MPAD_G 16512        // 129*128 padded rows for growth GEMM

// ---------------------------------------------------------------------------
// Static device scratch
// ---------------------------------------------------------------------------
__device__ float  g_res1f[(size_t)B_ * T_ * D_];
__device__ __half g_res1h[(size_t)B_ * T_ * D_];
__device__ float  g_rest [(size_t)B_ * D_ * T_];        // res transposed [b][d][t]
__device__ float  g_v    [(size_t)B_ * T_ * D_];
__device__ float  g_gtmp [(size_t)B_ * T_ * D_];        // growth partial states (fp32)
__device__ __half g_gpre [(size_t)MPAD_G * D_];         // half GEMM input (pad = 0)
__device__ float  g_res2f[(size_t)B_ * T_ * D_];
__device__ __half g_res2h[(size_t)B_ * T_ * D_];
__device__ __half g_hid  [(size_t)B_ * T_ * LAT_];
__device__ float  g_pre  [(size_t)B_ * T_ * D_];
__device__ float  g_gg   [(size_t)B_ * T_ * CO_];
__device__ float  g_ss   [(size_t)B_ * T_ * CO_];
__device__ float  g_tkA  [K_ * B_ * D_];                // re/512
__device__ float  g_tkB  [K_ * B_ * D_];                // im/512
__device__ int    g_tki  [K_ * B_ * D_];                // freq bin index
__device__ float  g_segf [(size_t)B_ * GSEG * D_];
__device__ float  g_lseg [LSEG * B_ * CO_];             // level segment finals
__device__ float2 g_trig [1024];                        // e^{+i 2pi j/1024}
// transposed + fp16-rounded weights [N][K]
__device__ __half g_win [(size_t)D_ * D_];
__device__ __half g_wout[(size_t)D_ * D_];
__device__ __half g_wf1 [(size_t)LAT_ * D_];
__device__ __half g_wf2 [(size_t)D_ * LAT_];

// ---------------------------------------------------------------------------
// Helpers
// ---------------------------------------------------------------------------
__device__ __forceinline__ uint32_t smem_u32(const void* p) {
    uint32_t a;
    asm("{ .reg .u64 t; cvta.to.shared.u64 t, %1; cvt.u32.u64 %0, t; }" : "=r"(a) : "l"(p));
    return a;
}
__device__ __forceinline__ void cp16(uint32_t dst, const void* src) {
    asm volatile("cp.async.cg.shared.global [%0], [%1], 16;" :: "r"(dst), "l"(src));
}
#define CP_COMMIT() asm volatile("cp.async.commit_group;" ::: "memory")

__device__ __forceinline__ void mma_f16(float* c, const uint32_t* a, const uint32_t* b) {
    asm volatile(
        "mma.sync.aligned.m16n8k16.row.col.f32.f16.f16.f32 "
        "{%0,%1,%2,%3}, {%4,%5,%6,%7}, {%8,%9}, {%0,%1,%2,%3};"
        : "+f"(c[0]), "+f"(c[1]), "+f"(c[2]), "+f"(c[3])
        : "r"(a[0]), "r"(a[1]), "r"(a[2]), "r"(a[3]), "r"(b[0]), "r"(b[1]));
}
__device__ __forceinline__ void ldsm4(uint32_t* r, uint32_t addr) {
    asm volatile("ldmatrix.sync.aligned.m8n8.x4.shared.b16 {%0,%1,%2,%3}, [%4];"
        : "=r"(r[0]), "=r"(r[1]), "=r"(r[2]), "=r"(r[3]) : "r"(addr));
}

// ---------------------------------------------------------------------------
// Kernel 0: fused prep — 4 weight transposes (fp32->fp16, [K,N]->[N,K]) + trig
//   grid.x = 2561 blocks of 256 threads
// ---------------------------------------------------------------------------
__device__ __forceinline__ void tr_body(const float* __restrict__ W,
        __half* __restrict__ WT, int K, int N, int n0, int k0) {
    __shared__ float t[32][33];
    int tx = threadIdx.x & 31, ty = threadIdx.x >> 5;   // 32x8
    #pragma unroll
    for (int i = 0; i < 32; i += 8)
        t[ty + i][tx] = W[(size_t)(k0 + ty + i) * N + n0 + tx];
    __syncthreads();
    #pragma unroll
    for (int i = 0; i < 32; i += 8)
        WT[(size_t)(n0 + ty + i) * K + k0 + tx] = __float2half_rn(t[tx][ty + i]);
}
__global__ __launch_bounds__(256) void prep_weights(const float* __restrict__ inw,
        const float* __restrict__ outw, const float* __restrict__ ffw1,
        const float* __restrict__ ffw2) {
    int id = blockIdx.x;
    if (id < 256) {
        tr_body(inw, g_win, D_, D_, (id & 15) * 32, (id >> 4) * 32);
    } else if (id < 512) {
        int i = id - 256;
        tr_body(outw, g_wout, D_, D_, (i & 15) * 32, (i >> 4) * 32);
    } else if (id < 1536) {
        int i = id - 512;                    // N = LAT (64 n-blocks), K = D (16)
        tr_body(ffw1, g_wf1, D_, LAT_, (i & 63) * 32, (i >> 6) * 32);
    } else if (id < 2560) {
        int i = id - 1536;                   // N = D (16 n-blocks), K = LAT (64)
        tr_body(ffw2, g_wf2, LAT_, D_, (i & 15) * 32, (i >> 4) * 32);
    } else {
        #pragma unroll
        for (int p = 0; p < 4; p++) {
            int i = threadIdx.x + p * 256;
            float s_, c_;
            sincosf(6.28318530717958647692f * ((float)i * (1.f / 1024.f)), &s_, &c_);
            g_trig[i] = make_float2(c_, s_);
        }
    }
}

// ---------------------------------------------------------------------------
// Kernel: res transpose [b][t][d] -> [b][d][t] (coalesced FFT input)
// ---------------------------------------------------------------------------
__global__ __launch_bounds__(256) void transpose_res(const float* __restrict__ X) {
    __shared__ float t[32][33];
    int d0 = blockIdx.x * 32, t0 = blockIdx.y * 32, b = blockIdx.z;
    int tx = threadIdx.x & 31, ty = threadIdx.x >> 5;
    #pragma unroll
    for (int i = 0; i < 32; i += 8)
        t[ty + i][tx] = X[((size_t)b * T_ + t0 + ty + i) * D_ + d0 + tx];
    __syncthreads();
    #pragma unroll
    for (int i = 0; i < 32; i += 8)
        g_rest[((size_t)b * D_ + d0 + ty + i) * T_ + t0 + tx] = t[tx][ty + i];
}

// ---------------------------------------------------------------------------
// Kernel 1: per-(b,d) 1024-pt FFT, TWO radix-2 stages per pass (bit-identical
//   ops/order to the 10-stage version), + top-8 selection. 256 threads.
// ---------------------------------------------------------------------------
__global__ __launch_bounds__(256) void fft_topk() {
    __shared__ float re[1024], im[1024], mag[512];
    __shared__ float twr[512], twi[512];
    __shared__ float wbv[8];
    __shared__ int   wbi[8];
    int bd  = blockIdx.x;
    int tid = threadIdx.x;
    const float* x = g_rest + (size_t)bd * T_;

    for (int i = tid; i < 512; i += 256) {
        float2 t = g_trig[i];
        twr[i] = t.x; twi[i] = -t.y;     // forward = conjugate
    }
    for (int t = tid; t < 1024; t += 256) {
        int r = __brev((unsigned)t) >> 22;
        re[r] = x[t];
        im[r] = 0.f;
    }
    __syncthreads();

    // 5 passes, each = radix-2 stages s and s+1 done in registers
    #pragma unroll
    for (int s = 1; s <= 9; s += 2) {
        int h = 1 << (s - 1);
        int k = tid & (h - 1);
        int i0 = ((tid >> (s - 1)) << (s + 1)) + k;
        int i1 = i0 + h, i2 = i0 + 2 * h, i3 = i0 + 3 * h;
        // stage s twiddle (same for both pairs)
        int  t1 = k << (10 - s);
        float w1r = twr[t1], w1i = twi[t1];
        float e0r = re[i0], e0i = im[i0];
        float e1r = re[i1], e1i = im[i1];
        float e2r = re[i2], e2i = im[i2];
        float e3r = re[i3], e3i = im[i3];
        // stage s: (e0,e1) and (e2,e3)
        float tr = w1r * e1r - w1i * e1i, ti = w1r * e1i + w1i * e1r;
        float a0r = e0r + tr, a0i = e0i + ti;
        float a1r = e0r - tr, a1i = e0i - ti;
        tr = w1r * e3r - w1i * e3i; ti = w1r * e3i + w1i * e3r;
        float a2r = e2r + tr, a2i = e2i + ti;
        float a3r = e2r - tr, a3i = e2i - ti;
        // stage s+1: (a0,a2) with k, (a1,a3) with k+h
        int t2a = k << (9 - s), t2b = (k + h) << (9 - s);
        float w2r = twr[t2a], w2i = twi[t2a];
        tr = w2r * a2r - w2i * a2i; ti = w2r * a2i + w2i * a2r;
        re[i0] = a0r + tr; im[i0] = a0i + ti;
        re[i2] = a0r - tr; im[i2] = a0i - ti;
        w2r = twr[t2b]; w2i = twi[t2b];
        tr = w2r * a3r - w2i * a3i; ti = w2r * a3i + w2i * a3r;
        re[i1] = a1r + tr; im[i1] = a1i + ti;
        re[i3] = a1r - tr; im[i3] = a1i - ti;
        __syncthreads();
    }

    for (int f = tid; f < 512; f += 256)
        mag[f] = (f == 0) ? -1.f : re[f] * re[f] + im[f] * im[f];
    __syncthreads();

    for (int kk = 0; kk < K_; kk++) {
        float best = -2.f; int bidx = 0;
        for (int f = tid; f < 512; f += 256) {
            float m = mag[f];
            if (m > best) { best = m; bidx = f; }
        }
        #pragma unroll
        for (int o = 16; o; o >>= 1) {
            float ob = __shfl_down_sync(0xffffffffu, best, o);
            int   oi = __shfl_down_sync(0xffffffffu, bidx, o);
            if (ob > best) { best = ob; bidx = oi; }
        }
        if ((tid & 31) == 0) { wbv[tid >> 5] = best; wbi[tid >> 5] = bidx; }
        __syncthreads();
        if (tid == 0) {
            for (int w = 1; w < 8; w++)
                if (wbv[w] > best) { best = wbv[w]; bidx = wbi[w]; }
            g_tkA[kk * (B_ * D_) + bd] = re[bidx] * (1.f / 512.f);
            g_tkB[kk * (B_ * D_) + bd] = im[bidx] * (1.f / 512.f);
            g_tki[kk * (B_ * D_) + bd] = bidx;
            mag[bidx] = -1.f;
        }
        __syncthreads();
    }
}

// ---------------------------------------------------------------------------
// Kernel 2: season synthesis (exact integer angle reduction + float2 table)
// ---------------------------------------------------------------------------
__global__ __launch_bounds__(256) void season_k(const float* __restrict__ res,
                                                float* __restrict__ season_out) {
    __shared__ float sA[K_][256], sB[K_][256];
    __shared__ int   sI[K_][256];
    __shared__ float2 tt[1024];
    int tid = threadIdx.x;
    int d   = blockIdx.x * 256 + tid;
    int b   = blockIdx.z;
    int bd  = b * D_ + d;
    for (int i = tid; i < 1024; i += 256) tt[i] = g_trig[i];
    #pragma unroll
    for (int k = 0; k < K_; k++) {
        sA[k][tid] = g_tkA[k * (B_ * D_) + bd];
        sB[k][tid] = g_tkB[k * (B_ * D_) + bd];
        sI[k][tid] = g_tki[k * (B_ * D_) + bd];
    }
    __syncthreads();
    int t0 = blockIdx.y * 16;
    for (int tt_i = 0; tt_i < 16; tt_i++) {
        int t = t0 + tt_i;
        float sum = 0.f;
        #pragma unroll
        for (int k = 0; k < K_; k++) {
            int m = (sI[k][tid] * t) & 1023;
            float2 cs = tt[m];
            sum += sA[k][tid] * cs.x - sB[k][tid] * cs.y;
        }
        season_out[((size_t)b * TP_ + t) * D_ + d] = sum;
        if (t < T_) {
            size_t ro = ((size_t)b * T_ + t) * D_ + d;
            float r1 = res[ro] - sum;
            g_res1f[ro] = r1;
            g_res1h[ro] = __float2half_rn(r1);
        }
    }
}

// ---------------------------------------------------------------------------
// Kernel 3: fp16 mma.sync GEMM (m16n8k16), ldmatrix, 4-stage cp.async.
//   CTA 128x128, 8 warps (4x2), warp tile 32x64, K-step 32.
// ---------------------------------------------------------------------------
#define RP_ 80
#define STAGE_B (256 * RP_)
__global__ void __launch_bounds__(256, 2)
gemm_h(int M, int N, int K,
       const __half* __restrict__ A, const __half* __restrict__ BT,
       float* __restrict__ Cf, __half* __restrict__ Ch,
       int epi, const float* __restrict__ ADD) {
    extern __shared__ char smc[];
    uint32_t s0 = smem_u32(smc);
    int tid = threadIdx.x, wid = tid >> 5, lane = tid & 31;
    int wr = wid >> 1, wc = wid & 1;
    int g = lane >> 2, tg = lane & 3;
    int row0 = blockIdx.y * 128, col0 = blockIdx.x * 128;
    int lr = lane & 15, lcb = (lane >> 4) * 16;

    float acc[2][8][4];
    #pragma unroll
    for (int i = 0; i < 2; i++)
        #pragma unroll
        for (int j = 0; j < 8; j++)
            #pragma unroll
            for (int q = 0; q < 4; q++) acc[i][j][q] = 0.f;

    const int S = K >> 5;
    auto issue = [&](int s) {
        int buf = s & 3;
        int k0 = s * 32;
        uint32_t da = s0 + buf * STAGE_B;
        uint32_t db = da + 128 * RP_;
        #pragma unroll
        for (int p = 0; p < 2; p++) {
            int c = tid + p * 256;
            int r = c >> 2, q = c & 3;
            cp16(da + r * RP_ + q * 16, A + (size_t)(row0 + r) * K + k0 + q * 8);
        }
        #pragma unroll
        for (int p = 0; p < 2; p++) {
            int c = tid + p * 256;
            int r = c >> 2, q = c & 3;
            cp16(db + r * RP_ + q * 16, BT + (size_t)(col0 + r) * K + k0 + q * 8);
        }
        CP_COMMIT();
    };

    issue(0);
    if (S > 1) issue(1);
    if (S > 2) issue(2);
    for (int s = 0; s < S; s++) {
        int buf = s & 3;
        if (s + 3 < S) {
            issue(s + 3);
            asm volatile("cp.async.wait_group 3;" ::: "memory");
        } else if (s + 2 < S) {
            asm volatile("cp.async.wait_group 2;" ::: "memory");
        } else if (s + 1 < S) {
            asm volatile("cp.async.wait_group 1;" ::: "memory");
        } else {
            asm volatile("cp.async.wait_group 0;" ::: "memory");
        }
        __syncthreads();
        uint32_t sa = s0 + buf * STAGE_B;
        uint32_t sb = sa + 128 * RP_;
        #pragma unroll
        for (int kh = 0; kh < 2; kh++) {
            uint32_t af[2][4], bf[8][2];
            #pragma unroll
            for (int mi = 0; mi < 2; mi++)
                ldsm4(af[mi], sa + (uint32_t)((wr * 32 + mi * 16 + lr) * RP_ + lcb + kh * 32));
            #pragma unroll
            for (int nt = 0; nt < 4; nt++) {
                uint32_t tb[4];
                ldsm4(tb, sb + (uint32_t)((wc * 64 + nt * 16 + lr) * RP_ + lcb + kh * 32));
                bf[nt * 2][0]     = tb[0]; bf[nt * 2][1]     = tb[2];
                bf[nt * 2 + 1][0] = tb[1]; bf[nt * 2 + 1][1] = tb[3];
            }
            #pragma unroll
            for (int mi = 0; mi < 2; mi++)
                #pragma unroll
                for (int ni = 0; ni < 8; ni++)
                    mma_f16(acc[mi][ni], af[mi], bf[ni]);
        }
        __syncthreads();
    }

    #pragma unroll
    for (int mi = 0; mi < 2; mi++) {
        #pragma unroll
        for (int hh = 0; hh < 2; hh++) {
            int r = row0 + wr * 32 + mi * 16 + g + hh * 8;
            if (r >= M) continue;
            #pragma unroll
            for (int ni = 0; ni < 8; ni++) {
                int c = col0 + wc * 64 + ni * 8 + tg * 2;
                float v0 = acc[mi][ni][hh * 2 + 0];
                float v1 = acc[mi][ni][hh * 2 + 1];
                if (epi == 1) {
                    v0 = 0.5f * v0 * (1.f + erff(v0 * 0.70710678118654752440f));
                    v1 = 0.5f * v1 * (1.f + erff(v1 * 0.70710678118654752440f));
                    *(__half2*)(Ch + (size_t)r * N + c) = __floats2half2_rn(v0, v1);
                } else {
                    if (epi == 2) {
                        const float* arow = ADD + (size_t)r * N;
                        v0 += arow[c]; v1 += arow[c + 1];
                    }
                    *(float2*)(Cf + (size_t)r * N + c) = make_float2(v0, v1);
                }
            }
        }
    }
}

// ---------------------------------------------------------------------------
// Kernel 4a: growth EMA partial scans -> g_gtmp (fp32), segment finals
// ---------------------------------------------------------------------------
__global__ __launch_bounds__(512) void growth_part(const float* __restrict__ z0,
        const float* __restrict__ sw) {
    int b = blockIdx.x, seg = blockIdx.y;
    int d = threadIdx.x;
    float w  = 1.f / (1.f + expf(-sw[d >> 6]));
    float om = 1.f - w;
    int t0 = seg * 64;
    const float* vp = g_v + ((size_t)b * T_ + t0) * D_ + d;
    float prev = (t0 == 0) ? z0[d] : vp[-(int)D_];
    float st = 0.f;
    float* gp = g_gtmp + ((size_t)b * T_ + t0) * D_ + d;
    #pragma unroll 8
    for (int t = 0; t < 64; t++) {
        float cur = vp[(size_t)t * D_];
        st = w * st + om * (cur - prev);
        prev = cur;
        gp[(size_t)t * D_] = st;
    }
    g_segf[((size_t)b * GSEG + seg) * D_ + d] = st;
}

// ---------------------------------------------------------------------------
// Kernel 4b: recombine + single rounding fp32 -> half into g_gpre
// ---------------------------------------------------------------------------
__global__ __launch_bounds__(512) void growth_apply(const float* __restrict__ sw,
        const float* __restrict__ v0) {
    int b = blockIdx.x, seg = blockIdx.y;
    int d = threadIdx.x;
    float w = 1.f / (1.f + expf(-sw[d >> 6]));
    float w2 = w * w, w4 = w2 * w2, w8 = w4 * w4, w16 = w8 * w8, w32 = w16 * w16;
    float wL = w32 * w32;
    float s_in = v0[d];
    for (int j = 0; j < seg; j++)
        s_in = wL * s_in + g_segf[((size_t)b * GSEG + j) * D_ + d];
    if (seg == 0)
        g_gpre[((size_t)b * T1_) * D_ + d] = __float2half_rn(v0[d]);
    const float* pp = g_gtmp + ((size_t)b * T_ + seg * 64) * D_ + d;
    __half* gp = g_gpre + ((size_t)b * T1_ + seg * 64 + 1) * D_ + d;
    float wp = w;
    #pragma unroll 8
    for (int t = 0; t < 64; t++) {
        gp[(size_t)t * D_] = __float2half_rn(pp[(size_t)t * D_] + wp * s_in);
        wp *= w;
    }
}

// ---------------------------------------------------------------------------
// Kernel 5: LayerNorm over D=512. If G: x = A - growth[b,t+1].
// ---------------------------------------------------------------------------
__global__ __launch_bounds__(128) void ln_k(const float* __restrict__ A,
        const float* __restrict__ G, const float* __restrict__ gam,
        const float* __restrict__ bet, float* __restrict__ outF,
        __half* __restrict__ outH) {
    __shared__ float sh[4], sh2[4];
    int row = blockIdx.x;
    int tid = threadIdx.x;
    const float* a = A + (size_t)row * D_;
    float x[4];
    if (G) {
        int b = row >> 10, t = row & 1023;
        const float* g = G + ((size_t)b * T1_ + t + 1) * D_;
        #pragma unroll
        for (int i = 0; i < 4; i++) x[i] = a[tid + i * 128] - g[tid + i * 128];
    } else {
        #pragma unroll
        for (int i = 0; i < 4; i++) x[i] = a[tid + i * 128];
    }
    float s = x[0] + x[1] + x[2] + x[3];
    #pragma unroll
    for (int o = 16; o; o >>= 1) s += __shfl_down_sync(0xffffffffu, s, o);
    if ((tid & 31) == 0) sh[tid >> 5] = s;
    __syncthreads();
    float mu = (sh[0] + sh[1] + sh[2] + sh[3]) * (1.f / 512.f);
    float vs = 0.f;
    #pragma unroll
    for (int i = 0; i < 4; i++) { float dx = x[i] - mu; vs += dx * dx; }
    #pragma unroll
    for (int o = 16; o; o >>= 1) vs += __shfl_down_sync(0xffffffffu, vs, o);
    if ((tid & 31) == 0) sh2[tid >> 5] = vs;
    __syncthreads();
    float var = (sh2[0] + sh2[1] + sh2[2] + sh2[3]) * (1.f / 512.f);
    float inv = rsqrtf(var + 1e-5f);
    float* oF = outF + (size_t)row * D_;
    __half* oH = outH ? outH + (size_t)row * D_ : nullptr;
    #pragma unroll
    for (int i = 0; i < 4; i++) {
        int c = tid + i * 128;
        float v = (x[i] - mu) * inv * gam[c] + bet[c];
        oF[c] = v;
        if (oH) oH[c] = __float2half_rn(v);
    }
}

// ---------------------------------------------------------------------------
// Kernel 6: fused skinny projections
// ---------------------------------------------------------------------------
__global__ __launch_bounds__(256) void skinny2(const float* __restrict__ growth,
        const float* __restrict__ season, const float* __restrict__ gpw,
        const float* __restrict__ spw) {
    __shared__ float xs[512];
    int which = blockIdx.y;
    int r = blockIdx.x;
    int b = r >> 10, t = r & 1023;
    const float* X = which ? season + (size_t)b * TP_ * D_ + (size_t)t * D_
                           : growth + (size_t)b * T1_ * D_ + (size_t)t * D_;
    const float* W = which ? spw : gpw;
    float* out = which ? g_ss : g_gg;
    for (int i = threadIdx.x; i < 512; i += 256) xs[i] = X[i];
    __syncthreads();
    int w = threadIdx.x >> 5, lane = threadIdx.x & 31;
    if (w < CO_) {
        float s = 0.f;
        for (int i = lane; i < 512; i += 32) s += xs[i] * W[i * CO_ + w];
        #pragma unroll
        for (int o = 16; o; o >>= 1) s += __shfl_down_sync(0xffffffffu, s, o);
        if (!lane) out[(size_t)r * CO_ + w] = s;
    }
}

// ---------------------------------------------------------------------------
// Kernel 7a: level EMA partial scans (zero init per 64-step segment)
//   out_level gets partial values; finals -> g_lseg
// ---------------------------------------------------------------------------
__global__ __launch_bounds__(128) void level_part(const float* __restrict__ level,
        const float* __restrict__ lsw, float* __restrict__ out) {
    int idx = threadIdx.x;
    if (idx >= B_ * CO_) return;
    int seg = blockIdx.x;
    int b = idx / CO_, c = idx % CO_;
    float w  = 1.f / (1.f + expf(-lsw[c]));
    float om = 1.f - w;
    int t0 = seg * 64;
    size_t base = (size_t)b * T_ * CO_ + (size_t)t0 * CO_ + c;
    const float* lp = level + base;
    const float* sp = g_ss  + base;
    const float* gp = g_gg  + base;
    float*       op = out   + base;
    float state = 0.f;
    #pragma unroll 4
    for (int t = 0; t < 64; t++) {
        float val = lp[t * CO_] - sp[t * CO_];
        state = w * state + om * val + w * gp[t * CO_];
        op[t * CO_] = state;
    }
    g_lseg[seg * (B_ * CO_) + idx] = state;
}

// ---------------------------------------------------------------------------
// Kernel 7b: level recombine: out += w^(tl+1) * carry
// ---------------------------------------------------------------------------
__global__ __launch_bounds__(128) void level_apply(const float* __restrict__ lsw,
        const float* __restrict__ lv0, float* __restrict__ out) {
    int idx = threadIdx.x;
    if (idx >= B_ * CO_) return;
    int seg = blockIdx.x;
    int b = idx / CO_, c = idx % CO_;
    float w = 1.f / (1.f + expf(-lsw[c]));
    float w2 = w * w, w4 = w2 * w2, w8 = w4 * w4, w16 = w8 * w8, w32 = w16 * w16;
    float wL = w32 * w32;
    float s_in = lv0[c];
    for (int j = 0; j < seg; j++)
        s_in = wL * s_in + g_lseg[j * (B_ * CO_) + idx];
    float* op = out + (size_t)b * T_ * CO_ + (size_t)(seg * 64) * CO_ + c;
    float wp = w;
    #pragma unroll 4
    for (int t = 0; t < 64; t++) {
        op[t * CO_] += wp * s_in;
        wp *= w;
    }
}

// ---------------------------------------------------------------------------
// Launch
// ---------------------------------------------------------------------------
extern "C" void kernel_launch(void* const* d_in, const int* in_sizes, int n_in,
                              void* d_out, int out_size) {
    const float* res  = (const float*)d_in[0];
    const float* lvl  = (const float*)d_in[1];
    const float* inw  = (const float*)d_in[2];
    const float* outw = (const float*)d_in[3];
    const float* z0   = (const float*)d_in[4];
    const float* gsw  = (const float*)d_in[5];
    const float* gv0  = (const float*)d_in[6];
    const float* ffw1 = (const float*)d_in[7];
    const float* ffw2 = (const float*)d_in[8];
    const float* n1g  = (const float*)d_in[9];
    const float* n1b  = (const float*)d_in[10];
    const float* n2g  = (const float*)d_in[11];
    const float* n2b  = (const float*)d_in[12];
    const float* gpw  = (const float*)d_in[13];
    const float* spw  = (const float*)d_in[14];
    const float* lsw  = (const float*)d_in[15];
    const float* lv0  = (const float*)d_in[16];

    float* out        = (float*)d_out;
    float* out_res3   = out;
    float* out_level  = out_res3  + (size_t)B_ * T_ * D_;
    float* out_growth = out_level + (size_t)B_ * T_ * CO_;
    float* out_season = out_growth + (size_t)B_ * T1_ * D_;

    float *p_res1f, *p_v, *p_res2f, *p_pre;
    __half *p_res1h, *p_gpre, *p_res2h, *p_hid;
    __half *p_win, *p_wout, *p_wf1, *p_wf2;
    cudaGetSymbolAddress((void**)&p_res1f, g_res1f);
    cudaGetSymbolAddress((void**)&p_res1h, g_res1h);
    cudaGetSymbolAddress((void**)&p_v,     g_v);
    cudaGetSymbolAddress((void**)&p_gpre,  g_gpre);
    cudaGetSymbolAddress((void**)&p_res2f, g_res2f);
    cudaGetSymbolAddress((void**)&p_res2h, g_res2h);
    cudaGetSymbolAddress((void**)&p_hid,   g_hid);
    cudaGetSymbolAddress((void**)&p_pre,   g_pre);
    cudaGetSymbolAddress((void**)&p_win,   g_win);
    cudaGetSymbolAddress((void**)&p_wout,  g_wout);
    cudaGetSymbolAddress((void**)&p_wf1,   g_wf1);
    cudaGetSymbolAddress((void**)&p_wf2,   g_wf2);

    const int GSMEM = 4 * STAGE_B;   // 81920 bytes
    static int smem_set = 0;
    if (!smem_set) {
        cudaFuncSetAttribute(gemm_h, cudaFuncAttributeMaxDynamicSharedMemorySize, GSMEM);
        smem_set = 1;
    }

    // 0. fused prep (weights + trig) and res transpose
    prep_weights<<<2561, 256>>>(inw, outw, ffw1, ffw2);
    transpose_res<<<dim3(D_ / 32, T_ / 32, B_), 256>>>(res);
    // 1. FFT + top-k
    fft_topk<<<B_ * D_, 256>>>();
    // 2. season + res1
    season_k<<<dim3(D_ / 256, TP_ / 16, B_), 256>>>(res, out_season);
    // 3. v = res1 @ in_w
    gemm_h<<<dim3(D_ / 128, (B_ * T_) / 128), 256, GSMEM>>>(
        B_ * T_, D_, D_, p_res1h, p_win, p_v, nullptr, 0, nullptr);
    // 4. growth EMA segmented scan
    growth_part<<<dim3(B_, GSEG), 512>>>(z0, gsw);
    growth_apply<<<dim3(B_, GSEG), 512>>>(gsw, gv0);
    // 5. growth = gpre @ out_w
    gemm_h<<<dim3(D_ / 128, (B_ * T1_ + 127) / 128), 256, GSMEM>>>(
        B_ * T1_, D_, D_, p_gpre, p_wout, out_growth, nullptr, 0, nullptr);
    // 6. res2 = LN1(res1 - growth[:,1:])
    ln_k<<<B_ * T_, 128>>>(p_res1f, out_growth, n1g, n1b, p_res2f, p_res2h);
    // 7. hid = gelu(res2 @ ff_w1) -> half
    gemm_h<<<dim3(LAT_ / 128, (B_ * T_) / 128), 256, GSMEM>>>(
        B_ * T_, LAT_, D_, p_res2h, p_wf1, nullptr, p_hid, 1, nullptr);
    // 8. pre = hid @ ff_w2 + res2
    gemm_h<<<dim3(D_ / 128, (B_ * T_) / 128), 256, GSMEM>>>(
        B_ * T_, D_, LAT_, p_hid, p_wf2, p_pre, nullptr, 2, p_res2f);
    // 9. res3 = LN2(pre)
    ln_k<<<B_ * T_, 128>>>(p_pre, nullptr, n2g, n2b, out_res3, nullptr);
    // 10. skinny projections
    skinny2<<<dim3(B_ * T_, 2), 256>>>(out_growth, out_season, gpw, spw);
    // 11. level EMA segmented scan
    level_part<<<LSEG, 128>>>(lvl, lsw, out_level);
    level_apply<<<LSEG, 128>>>(lsw, lv0, out_level);
}

// round 14
// speedup vs baseline: 4.1676x; 1.0920x over previous
#include <cuda_runtime.h>
#include <cuda_fp16.h>
#include <math.h>
#include <stdint.h>

// ---------------------------------------------------------------------------
// Problem constants
// ---------------------------------------------------------------------------
#define B_   16
#define T_   1024
#define D_   512
#define CO_  7
#define PRED_ 96
#define K_   8
#define LAT_ 2048
#define TP_  (T_ + PRED_)   // 1120
#define T1_  (T_ + 1)       // 1025
#define GSEG 16             // growth scan segments (64 steps each)
#define LSEG 16             // level scan segments (64 steps each)
#define MPAD_G 16512        // 129*128 padded rows for growth GEMM

// ---------------------------------------------------------------------------
// Static device scratch
// ---------------------------------------------------------------------------
__device__ float  g_res1f[(size_t)B_ * T_ * D_];
__device__ __half g_res1h[(size_t)B_ * T_ * D_];
__device__ float  g_rest [(size_t)B_ * D_ * T_];        // res transposed [b][d][t]
__device__ float  g_v    [(size_t)B_ * T_ * D_];
__device__ __half g_gpre [(size_t)MPAD_G * D_];         // half GEMM input (pad = 0)
__device__ float  g_res2f[(size_t)B_ * T_ * D_];
__device__ __half g_res2h[(size_t)B_ * T_ * D_];
__device__ __half g_hid  [(size_t)B_ * T_ * LAT_];
__device__ float  g_pre  [(size_t)B_ * T_ * D_];
__device__ float  g_gg   [(size_t)B_ * T_ * CO_];
__device__ float  g_ss   [(size_t)B_ * T_ * CO_];
__device__ float  g_tkA  [K_ * B_ * D_];                // re/512
__device__ float  g_tkB  [K_ * B_ * D_];                // im/512
__device__ int    g_tki  [K_ * B_ * D_];                // freq bin index
__device__ float  g_segf [(size_t)B_ * GSEG * D_];
__device__ float  g_lseg [LSEG * B_ * CO_];             // level segment finals
__device__ float2 g_trig [1024];                        // e^{+i 2pi j/1024}
// transposed + fp16-rounded weights [N][K]
__device__ __half g_win [(size_t)D_ * D_];
__device__ __half g_wout[(size_t)D_ * D_];
__device__ __half g_wf1 [(size_t)LAT_ * D_];
__device__ __half g_wf2 [(size_t)D_ * LAT_];

// ---------------------------------------------------------------------------
// Helpers
// ---------------------------------------------------------------------------
__device__ __forceinline__ uint32_t smem_u32(const void* p) {
    uint32_t a;
    asm("{ .reg .u64 t; cvta.to.shared.u64 t, %1; cvt.u32.u64 %0, t; }" : "=r"(a) : "l"(p));
    return a;
}
__device__ __forceinline__ void cp16(uint32_t dst, const void* src) {
    asm volatile("cp.async.cg.shared.global [%0], [%1], 16;" :: "r"(dst), "l"(src));
}
#define CP_COMMIT() asm volatile("cp.async.commit_group;" ::: "memory")

__device__ __forceinline__ void mma_f16(float* c, const uint32_t* a, const uint32_t* b) {
    asm volatile(
        "mma.sync.aligned.m16n8k16.row.col.f32.f16.f16.f32 "
        "{%0,%1,%2,%3}, {%4,%5,%6,%7}, {%8,%9}, {%0,%1,%2,%3};"
        : "+f"(c[0]), "+f"(c[1]), "+f"(c[2]), "+f"(c[3])
        : "r"(a[0]), "r"(a[1]), "r"(a[2]), "r"(a[3]), "r"(b[0]), "r"(b[1]));
}
__device__ __forceinline__ void ldsm4(uint32_t* r, uint32_t addr) {
    asm volatile("ldmatrix.sync.aligned.m8n8.x4.shared.b16 {%0,%1,%2,%3}, [%4];"
        : "=r"(r[0]), "=r"(r[1]), "=r"(r[2]), "=r"(r[3]) : "r"(addr));
}

// ---------------------------------------------------------------------------
// Kernel 0: fused prep — 4 weight transposes (fp32->fp16, [K,N]->[N,K]) + trig
// ---------------------------------------------------------------------------
__device__ __forceinline__ void tr_body(const float* __restrict__ W,
        __half* __restrict__ WT, int K, int N, int n0, int k0) {
    __shared__ float t[32][33];
    int tx = threadIdx.x & 31, ty = threadIdx.x >> 5;   // 32x8
    #pragma unroll
    for (int i = 0; i < 32; i += 8)
        t[ty + i][tx] = W[(size_t)(k0 + ty + i) * N + n0 + tx];
    __syncthreads();
    #pragma unroll
    for (int i = 0; i < 32; i += 8)
        WT[(size_t)(n0 + ty + i) * K + k0 + tx] = __float2half_rn(t[tx][ty + i]);
}
__global__ __launch_bounds__(256) void prep_weights(const float* __restrict__ inw,
        const float* __restrict__ outw, const float* __restrict__ ffw1,
        const float* __restrict__ ffw2) {
    int id = blockIdx.x;
    if (id < 256) {
        tr_body(inw, g_win, D_, D_, (id & 15) * 32, (id >> 4) * 32);
    } else if (id < 512) {
        int i = id - 256;
        tr_body(outw, g_wout, D_, D_, (i & 15) * 32, (i >> 4) * 32);
    } else if (id < 1536) {
        int i = id - 512;
        tr_body(ffw1, g_wf1, D_, LAT_, (i & 63) * 32, (i >> 6) * 32);
    } else if (id < 2560) {
        int i = id - 1536;
        tr_body(ffw2, g_wf2, LAT_, D_, (i & 15) * 32, (i >> 4) * 32);
    } else {
        #pragma unroll
        for (int p = 0; p < 4; p++) {
            int i = threadIdx.x + p * 256;
            float s_, c_;
            sincosf(6.28318530717958647692f * ((float)i * (1.f / 1024.f)), &s_, &c_);
            g_trig[i] = make_float2(c_, s_);
        }
    }
}

// ---------------------------------------------------------------------------
// Kernel: res transpose [b][t][d] -> [b][d][t] (coalesced FFT input)
// ---------------------------------------------------------------------------
__global__ __launch_bounds__(256) void transpose_res(const float* __restrict__ X) {
    __shared__ float t[32][33];
    int d0 = blockIdx.x * 32, t0 = blockIdx.y * 32, b = blockIdx.z;
    int tx = threadIdx.x & 31, ty = threadIdx.x >> 5;
    #pragma unroll
    for (int i = 0; i < 32; i += 8)
        t[ty + i][tx] = X[((size_t)b * T_ + t0 + ty + i) * D_ + d0 + tx];
    __syncthreads();
    #pragma unroll
    for (int i = 0; i < 32; i += 8)
        g_rest[((size_t)b * D_ + d0 + ty + i) * T_ + t0 + tx] = t[tx][ty + i];
}

// ---------------------------------------------------------------------------
// Kernel 1: per-(b,d) 1024-pt FFT, two radix-2 stages per pass, top-8.
// ---------------------------------------------------------------------------
__global__ __launch_bounds__(256) void fft_topk() {
    __shared__ float re[1024], im[1024], mag[512];
    __shared__ float twr[512], twi[512];
    __shared__ float wbv[8];
    __shared__ int   wbi[8];
    int bd  = blockIdx.x;
    int tid = threadIdx.x;
    const float* x = g_rest + (size_t)bd * T_;

    for (int i = tid; i < 512; i += 256) {
        float2 t = g_trig[i];
        twr[i] = t.x; twi[i] = -t.y;     // forward = conjugate
    }
    for (int t = tid; t < 1024; t += 256) {
        int r = __brev((unsigned)t) >> 22;
        re[r] = x[t];
        im[r] = 0.f;
    }
    __syncthreads();

    #pragma unroll
    for (int s = 1; s <= 9; s += 2) {
        int h = 1 << (s - 1);
        int k = tid & (h - 1);
        int i0 = ((tid >> (s - 1)) << (s + 1)) + k;
        int i1 = i0 + h, i2 = i0 + 2 * h, i3 = i0 + 3 * h;
        int  t1 = k << (10 - s);
        float w1r = twr[t1], w1i = twi[t1];
        float e0r = re[i0], e0i = im[i0];
        float e1r = re[i1], e1i = im[i1];
        float e2r = re[i2], e2i = im[i2];
        float e3r = re[i3], e3i = im[i3];
        float tr = w1r * e1r - w1i * e1i, ti = w1r * e1i + w1i * e1r;
        float a0r = e0r + tr, a0i = e0i + ti;
        float a1r = e0r - tr, a1i = e0i - ti;
        tr = w1r * e3r - w1i * e3i; ti = w1r * e3i + w1i * e3r;
        float a2r = e2r + tr, a2i = e2i + ti;
        float a3r = e2r - tr, a3i = e2i - ti;
        int t2a = k << (9 - s), t2b = (k + h) << (9 - s);
        float w2r = twr[t2a], w2i = twi[t2a];
        tr = w2r * a2r - w2i * a2i; ti = w2r * a2i + w2i * a2r;
        re[i0] = a0r + tr; im[i0] = a0i + ti;
        re[i2] = a0r - tr; im[i2] = a0i - ti;
        w2r = twr[t2b]; w2i = twi[t2b];
        tr = w2r * a3r - w2i * a3i; ti = w2r * a3i + w2i * a3r;
        re[i1] = a1r + tr; im[i1] = a1i + ti;
        re[i3] = a1r - tr; im[i3] = a1i - ti;
        __syncthreads();
    }

    for (int f = tid; f < 512; f += 256)
        mag[f] = (f == 0) ? -1.f : re[f] * re[f] + im[f] * im[f];
    __syncthreads();

    for (int kk = 0; kk < K_; kk++) {
        float best = -2.f; int bidx = 0;
        for (int f = tid; f < 512; f += 256) {
            float m = mag[f];
            if (m > best) { best = m; bidx = f; }
        }
        #pragma unroll
        for (int o = 16; o; o >>= 1) {
            float ob = __shfl_down_sync(0xffffffffu, best, o);
            int   oi = __shfl_down_sync(0xffffffffu, bidx, o);
            if (ob > best) { best = ob; bidx = oi; }
        }
        if ((tid & 31) == 0) { wbv[tid >> 5] = best; wbi[tid >> 5] = bidx; }
        __syncthreads();
        if (tid == 0) {
            for (int w = 1; w < 8; w++)
                if (wbv[w] > best) { best = wbv[w]; bidx = wbi[w]; }
            g_tkA[kk * (B_ * D_) + bd] = re[bidx] * (1.f / 512.f);
            g_tkB[kk * (B_ * D_) + bd] = im[bidx] * (1.f / 512.f);
            g_tki[kk * (B_ * D_) + bd] = bidx;
            mag[bidx] = -1.f;
        }
        __syncthreads();
    }
}

// ---------------------------------------------------------------------------
// Kernel 2: season synthesis via register rotation.
//   Per strip of 16 t: seed z_k from exact table entry at (f*t0)&1023,
//   rotate by table entry w_k = tt[f] each step (<=15 steps, ~2e-6 drift).
// ---------------------------------------------------------------------------
__global__ __launch_bounds__(256) void season_k(const float* __restrict__ res,
                                                float* __restrict__ season_out) {
    __shared__ float2 tt[1024];
    int tid = threadIdx.x;
    int d   = blockIdx.x * 256 + tid;
    int b   = blockIdx.z;
    int bd  = b * D_ + d;
    for (int i = tid; i < 1024; i += 256) tt[i] = g_trig[i];
    __syncthreads();
    int t0 = blockIdx.y * 16;

    float A[K_], Bv[K_], zr[K_], zi[K_], wr[K_], wi[K_];
    #pragma unroll
    for (int k = 0; k < K_; k++) {
        A[k]  = g_tkA[k * (B_ * D_) + bd];
        Bv[k] = g_tkB[k * (B_ * D_) + bd];
        int f = g_tki[k * (B_ * D_) + bd];
        float2 w = tt[f];
        wr[k] = w.x; wi[k] = w.y;
        float2 z = tt[(f * t0) & 1023];
        zr[k] = z.x; zi[k] = z.y;
    }

    #pragma unroll
    for (int ts = 0; ts < 16; ts++) {
        int t = t0 + ts;
        float sum = 0.f;
        #pragma unroll
        for (int k = 0; k < K_; k++) {
            sum += A[k] * zr[k] - Bv[k] * zi[k];
            float nr = zr[k] * wr[k] - zi[k] * wi[k];
            zi[k]    = zr[k] * wi[k] + zi[k] * wr[k];
            zr[k]    = nr;
        }
        season_out[((size_t)b * TP_ + t) * D_ + d] = sum;
        if (t < T_) {
            size_t ro = ((size_t)b * T_ + t) * D_ + d;
            float r1 = res[ro] - sum;
            g_res1f[ro] = r1;
            g_res1h[ro] = __float2half_rn(r1);
        }
    }
}

// ---------------------------------------------------------------------------
// Kernel 3: fp16 mma.sync GEMM (m16n8k16), ldmatrix, 4-stage cp.async.
// ---------------------------------------------------------------------------
#define RP_ 80
#define STAGE_B (256 * RP_)
__global__ void __launch_bounds__(256, 2)
gemm_h(int M, int N, int K,
       const __half* __restrict__ A, const __half* __restrict__ BT,
       float* __restrict__ Cf, __half* __restrict__ Ch,
       int epi, const float* __restrict__ ADD) {
    extern __shared__ char smc[];
    uint32_t s0 = smem_u32(smc);
    int tid = threadIdx.x, wid = tid >> 5, lane = tid & 31;
    int wr = wid >> 1, wc = wid & 1;
    int g = lane >> 2, tg = lane & 3;
    int row0 = blockIdx.y * 128, col0 = blockIdx.x * 128;
    int lr = lane & 15, lcb = (lane >> 4) * 16;

    float acc[2][8][4];
    #pragma unroll
    for (int i = 0; i < 2; i++)
        #pragma unroll
        for (int j = 0; j < 8; j++)
            #pragma unroll
            for (int q = 0; q < 4; q++) acc[i][j][q] = 0.f;

    const int S = K >> 5;
    auto issue = [&](int s) {
        int buf = s & 3;
        int k0 = s * 32;
        uint32_t da = s0 + buf * STAGE_B;
        uint32_t db = da + 128 * RP_;
        #pragma unroll
        for (int p = 0; p < 2; p++) {
            int c = tid + p * 256;
            int r = c >> 2, q = c & 3;
            cp16(da + r * RP_ + q * 16, A + (size_t)(row0 + r) * K + k0 + q * 8);
        }
        #pragma unroll
        for (int p = 0; p < 2; p++) {
            int c = tid + p * 256;
            int r = c >> 2, q = c & 3;
            cp16(db + r * RP_ + q * 16, BT + (size_t)(col0 + r) * K + k0 + q * 8);
        }
        CP_COMMIT();
    };

    issue(0);
    if (S > 1) issue(1);
    if (S > 2) issue(2);
    for (int s = 0; s < S; s++) {
        int buf = s & 3;
        if (s + 3 < S) {
            issue(s + 3);
            asm volatile("cp.async.wait_group 3;" ::: "memory");
        } else if (s + 2 < S) {
            asm volatile("cp.async.wait_group 2;" ::: "memory");
        } else if (s + 1 < S) {
            asm volatile("cp.async.wait_group 1;" ::: "memory");
        } else {
            asm volatile("cp.async.wait_group 0;" ::: "memory");
        }
        __syncthreads();
        uint32_t sa = s0 + buf * STAGE_B;
        uint32_t sb = sa + 128 * RP_;
        #pragma unroll
        for (int kh = 0; kh < 2; kh++) {
            uint32_t af[2][4], bf[8][2];
            #pragma unroll
            for (int mi = 0; mi < 2; mi++)
                ldsm4(af[mi], sa + (uint32_t)((wr * 32 + mi * 16 + lr) * RP_ + lcb + kh * 32));
            #pragma unroll
            for (int nt = 0; nt < 4; nt++) {
                uint32_t tb[4];
                ldsm4(tb, sb + (uint32_t)((wc * 64 + nt * 16 + lr) * RP_ + lcb + kh * 32));
                bf[nt * 2][0]     = tb[0]; bf[nt * 2][1]     = tb[2];
                bf[nt * 2 + 1][0] = tb[1]; bf[nt * 2 + 1][1] = tb[3];
            }
            #pragma unroll
            for (int mi = 0; mi < 2; mi++)
                #pragma unroll
                for (int ni = 0; ni < 8; ni++)
                    mma_f16(acc[mi][ni], af[mi], bf[ni]);
        }
        __syncthreads();
    }

    #pragma unroll
    for (int mi = 0; mi < 2; mi++) {
        #pragma unroll
        for (int hh = 0; hh < 2; hh++) {
            int r = row0 + wr * 32 + mi * 16 + g + hh * 8;
            if (r >= M) continue;
            #pragma unroll
            for (int ni = 0; ni < 8; ni++) {
                int c = col0 + wc * 64 + ni * 8 + tg * 2;
                float v0 = acc[mi][ni][hh * 2 + 0];
                float v1 = acc[mi][ni][hh * 2 + 1];
                if (epi == 1) {
                    v0 = 0.5f * v0 * (1.f + erff(v0 * 0.70710678118654752440f));
                    v1 = 0.5f * v1 * (1.f + erff(v1 * 0.70710678118654752440f));
                    *(__half2*)(Ch + (size_t)r * N + c) = __floats2half2_rn(v0, v1);
                } else {
                    if (epi == 2) {
                        const float* arow = ADD + (size_t)r * N;
                        v0 += arow[c]; v1 += arow[c + 1];
                    }
                    *(float2*)(Cf + (size_t)r * N + c) = make_float2(v0, v1);
                }
            }
        }
    }
}

// ---------------------------------------------------------------------------
// Kernel 4a: growth EMA segment finals only (no partial stores)
// ---------------------------------------------------------------------------
__global__ __launch_bounds__(512) void growth_fin(const float* __restrict__ z0,
        const float* __restrict__ sw) {
    int b = blockIdx.x, seg = blockIdx.y;
    int d = threadIdx.x;
    float w  = 1.f / (1.f + expf(-sw[d >> 6]));
    float om = 1.f - w;
    int t0 = seg * 64;
    const float* vp = g_v + ((size_t)b * T_ + t0) * D_ + d;
    float prev = (t0 == 0) ? z0[d] : vp[-(int)D_];
    float st = 0.f;
    #pragma unroll 8
    for (int t = 0; t < 64; t++) {
        float cur = vp[(size_t)t * D_];
        st = w * st + om * (cur - prev);
        prev = cur;
    }
    g_segf[((size_t)b * GSEG + seg) * D_ + d] = st;
}

// ---------------------------------------------------------------------------
// Kernel 4b: growth rescan with correct carry, write half directly
// ---------------------------------------------------------------------------
__global__ __launch_bounds__(512) void growth_scan2(const float* __restrict__ z0,
        const float* __restrict__ sw, const float* __restrict__ v0) {
    int b = blockIdx.x, seg = blockIdx.y;
    int d = threadIdx.x;
    float w = 1.f / (1.f + expf(-sw[d >> 6]));
    float om = 1.f - w;
    float w2 = w * w, w4 = w2 * w2, w8 = w4 * w4, w16 = w8 * w8, w32 = w16 * w16;
    float wL = w32 * w32;
    float s_in = v0[d];
    for (int j = 0; j < seg; j++)
        s_in = wL * s_in + g_segf[((size_t)b * GSEG + j) * D_ + d];
    if (seg == 0)
        g_gpre[((size_t)b * T1_) * D_ + d] = __float2half_rn(v0[d]);
    int t0 = seg * 64;
    const float* vp = g_v + ((size_t)b * T_ + t0) * D_ + d;
    float prev = (t0 == 0) ? z0[d] : vp[-(int)D_];
    __half* gp = g_gpre + ((size_t)b * T1_ + t0 + 1) * D_ + d;
    float st = s_in;
    #pragma unroll 8
    for (int t = 0; t < 64; t++) {
        float cur = vp[(size_t)t * D_];
        st = w * st + om * (cur - prev);
        prev = cur;
        gp[(size_t)t * D_] = __float2half_rn(st);
    }
}

// ---------------------------------------------------------------------------
// Kernel 5: LayerNorm over D=512. If G: x = A - growth[b,t+1].
// ---------------------------------------------------------------------------
__global__ __launch_bounds__(128) void ln_k(const float* __restrict__ A,
        const __half* __restrict__ G, const float* __restrict__ gam,
        const float* __restrict__ bet, float* __restrict__ outF,
        __half* __restrict__ outH) {
    __shared__ float sh[4], sh2[4];
    int row = blockIdx.x;
    int tid = threadIdx.x;
    const float* a = A + (size_t)row * D_;
    float x[4];
    if (G) {
        int b = row >> 10, t = row & 1023;
        const __half* g = G + ((size_t)b * T1_ + t + 1) * D_;
        #pragma unroll
        for (int i = 0; i < 4; i++)
            x[i] = a[tid + i * 128] - __half2float(g[tid + i * 128]);
    } else {
        #pragma unroll
        for (int i = 0; i < 4; i++) x[i] = a[tid + i * 128];
    }
    float s = x[0] + x[1] + x[2] + x[3];
    #pragma unroll
    for (int o = 16; o; o >>= 1) s += __shfl_down_sync(0xffffffffu, s, o);
    if ((tid & 31) == 0) sh[tid >> 5] = s;
    __syncthreads();
    float mu = (sh[0] + sh[1] + sh[2] + sh[3]) * (1.f / 512.f);
    float vs = 0.f;
    #pragma unroll
    for (int i = 0; i < 4; i++) { float dx = x[i] - mu; vs += dx * dx; }
    #pragma unroll
    for (int o = 16; o; o >>= 1) vs += __shfl_down_sync(0xffffffffu, vs, o);
    if ((tid & 31) == 0) sh2[tid >> 5] = vs;
    __syncthreads();
    float var = (sh2[0] + sh2[1] + sh2[2] + sh2[3]) * (1.f / 512.f);
    float inv = rsqrtf(var + 1e-5f);
    float* oF = outF + (size_t)row * D_;
    __half* oH = outH ? outH + (size_t)row * D_ : nullptr;
    #pragma unroll
    for (int i = 0; i < 4; i++) {
        int c = tid + i * 128;
        float v = (x[i] - mu) * inv * gam[c] + bet[c];
        oF[c] = v;
        if (oH) oH[c] = __float2half_rn(v);
    }
}

// NOTE: LN1 consumed fp32 growth before; it now reads the half-rounded growth
// (same values the reference-divergence already contains via the GEMM), but
// growth OUTPUT must stay fp32 — so growth GEMM still writes out_growth fp32
// and we subtract that. Keep fp32 path: see launch (G passed as fp32 variant).

// fp32-G variant of ln_k (used for LN1; avoids extra rounding of growth)
__global__ __launch_bounds__(128) void ln_kf(const float* __restrict__ A,
        const float* __restrict__ G, const float* __restrict__ gam,
        const float* __restrict__ bet, float* __restrict__ outF,
        __half* __restrict__ outH) {
    __shared__ float sh[4], sh2[4];
    int row = blockIdx.x;
    int tid = threadIdx.x;
    const float* a = A + (size_t)row * D_;
    float x[4];
    if (G) {
        int b = row >> 10, t = row & 1023;
        const float* g = G + ((size_t)b * T1_ + t + 1) * D_;
        #pragma unroll
        for (int i = 0; i < 4; i++) x[i] = a[tid + i * 128] - g[tid + i * 128];
    } else {
        #pragma unroll
        for (int i = 0; i < 4; i++) x[i] = a[tid + i * 128];
    }
    float s = x[0] + x[1] + x[2] + x[3];
    #pragma unroll
    for (int o = 16; o; o >>= 1) s += __shfl_down_sync(0xffffffffu, s, o);
    if ((tid & 31) == 0) sh[tid >> 5] = s;
    __syncthreads();
    float mu = (sh[0] + sh[1] + sh[2] + sh[3]) * (1.f / 512.f);
    float vs = 0.f;
    #pragma unroll
    for (int i = 0; i < 4; i++) { float dx = x[i] - mu; vs += dx * dx; }
    #pragma unroll
    for (int o = 16; o; o >>= 1) vs += __shfl_down_sync(0xffffffffu, vs, o);
    if ((tid & 31) == 0) sh2[tid >> 5] = vs;
    __syncthreads();
    float var = (sh2[0] + sh2[1] + sh2[2] + sh2[3]) * (1.f / 512.f);
    float inv = rsqrtf(var + 1e-5f);
    float* oF = outF + (size_t)row * D_;
    __half* oH = outH ? outH + (size_t)row * D_ : nullptr;
    #pragma unroll
    for (int i = 0; i < 4; i++) {
        int c = tid + i * 128;
        float v = (x[i] - mu) * inv * gam[c] + bet[c];
        oF[c] = v;
        if (oH) oH[c] = __float2half_rn(v);
    }
}

// ---------------------------------------------------------------------------
// Kernel 6: fused skinny projections
// ---------------------------------------------------------------------------
__global__ __launch_bounds__(256) void skinny2(const float* __restrict__ growth,
        const float* __restrict__ season, const float* __restrict__ gpw,
        const float* __restrict__ spw) {
    __shared__ float xs[512];
    int which = blockIdx.y;
    int r = blockIdx.x;
    int b = r >> 10, t = r & 1023;
    const float* X = which ? season + (size_t)b * TP_ * D_ + (size_t)t * D_
                           : growth + (size_t)b * T1_ * D_ + (size_t)t * D_;
    const float* W = which ? spw : gpw;
    float* out = which ? g_ss : g_gg;
    for (int i = threadIdx.x; i < 512; i += 256) xs[i] = X[i];
    __syncthreads();
    int w = threadIdx.x >> 5, lane = threadIdx.x & 31;
    if (w < CO_) {
        float s = 0.f;
        for (int i = lane; i < 512; i += 32) s += xs[i] * W[i * CO_ + w];
        #pragma unroll
        for (int o = 16; o; o >>= 1) s += __shfl_down_sync(0xffffffffu, s, o);
        if (!lane) out[(size_t)r * CO_ + w] = s;
    }
}

// ---------------------------------------------------------------------------
// Kernel 7a/7b: level EMA segmented scan
// ---------------------------------------------------------------------------
__global__ __launch_bounds__(128) void level_part(const float* __restrict__ level,
        const float* __restrict__ lsw, float* __restrict__ out) {
    int idx = threadIdx.x;
    if (idx >= B_ * CO_) return;
    int seg = blockIdx.x;
    int b = idx / CO_, c = idx % CO_;
    float w  = 1.f / (1.f + expf(-lsw[c]));
    float om = 1.f - w;
    int t0 = seg * 64;
    size_t base = (size_t)b * T_ * CO_ + (size_t)t0 * CO_ + c;
    const float* lp = level + base;
    const float* sp = g_ss  + base;
    const float* gp = g_gg  + base;
    float*       op = out   + base;
    float state = 0.f;
    #pragma unroll 4
    for (int t = 0; t < 64; t++) {
        float val = lp[t * CO_] - sp[t * CO_];
        state = w * state + om * val + w * gp[t * CO_];
        op[t * CO_] = state;
    }
    g_lseg[seg * (B_ * CO_) + idx] = state;
}
__global__ __launch_bounds__(128) void level_apply(const float* __restrict__ lsw,
        const float* __restrict__ lv0, float* __restrict__ out) {
    int idx = threadIdx.x;
    if (idx >= B_ * CO_) return;
    int seg = blockIdx.x;
    int b = idx / CO_, c = idx % CO_;
    float w = 1.f / (1.f + expf(-lsw[c]));
    float w2 = w * w, w4 = w2 * w2, w8 = w4 * w4, w16 = w8 * w8, w32 = w16 * w16;
    float wL = w32 * w32;
    float s_in = lv0[c];
    for (int j = 0; j < seg; j++)
        s_in = wL * s_in + g_lseg[j * (B_ * CO_) + idx];
    float* op = out + (size_t)b * T_ * CO_ + (size_t)(seg * 64) * CO_ + c;
    float wp = w;
    #pragma unroll 4
    for (int t = 0; t < 64; t++) {
        op[t * CO_] += wp * s_in;
        wp *= w;
    }
}

// ---------------------------------------------------------------------------
// Launch
// ---------------------------------------------------------------------------
extern "C" void kernel_launch(void* const* d_in, const int* in_sizes, int n_in,
                              void* d_out, int out_size) {
    const float* res  = (const float*)d_in[0];
    const float* lvl  = (const float*)d_in[1];
    const float* inw  = (const float*)d_in[2];
    const float* outw = (const float*)d_in[3];
    const float* z0   = (const float*)d_in[4];
    const float* gsw  = (const float*)d_in[5];
    const float* gv0  = (const float*)d_in[6];
    const float* ffw1 = (const float*)d_in[7];
    const float* ffw2 = (const float*)d_in[8];
    const float* n1g  = (const float*)d_in[9];
    const float* n1b  = (const float*)d_in[10];
    const float* n2g  = (const float*)d_in[11];
    const float* n2b  = (const float*)d_in[12];
    const float* gpw  = (const float*)d_in[13];
    const float* spw  = (const float*)d_in[14];
    const float* lsw  = (const float*)d_in[15];
    const float* lv0  = (const float*)d_in[16];

    float* out        = (float*)d_out;
    float* out_res3   = out;
    float* out_level  = out_res3  + (size_t)B_ * T_ * D_;
    float* out_growth = out_level + (size_t)B_ * T_ * CO_;
    float* out_season = out_growth + (size_t)B_ * T1_ * D_;

    float *p_res1f, *p_v, *p_res2f, *p_pre;
    __half *p_res1h, *p_gpre, *p_res2h, *p_hid;
    __half *p_win, *p_wout, *p_wf1, *p_wf2;
    cudaGetSymbolAddress((void**)&p_res1f, g_res1f);
    cudaGetSymbolAddress((void**)&p_res1h, g_res1h);
    cudaGetSymbolAddress((void**)&p_v,     g_v);
    cudaGetSymbolAddress((void**)&p_gpre,  g_gpre);
    cudaGetSymbolAddress((void**)&p_res2f, g_res2f);
    cudaGetSymbolAddress((void**)&p_res2h, g_res2h);
    cudaGetSymbolAddress((void**)&p_hid,   g_hid);
    cudaGetSymbolAddress((void**)&p_pre,   g_pre);
    cudaGetSymbolAddress((void**)&p_win,   g_win);
    cudaGetSymbolAddress((void**)&p_wout,  g_wout);
    cudaGetSymbolAddress((void**)&p_wf1,   g_wf1);
    cudaGetSymbolAddress((void**)&p_wf2,   g_wf2);

    const int GSMEM = 4 * STAGE_B;   // 81920 bytes
    static int smem_set = 0;
    if (!smem_set) {
        cudaFuncSetAttribute(gemm_h, cudaFuncAttributeMaxDynamicSharedMemorySize, GSMEM);
        smem_set = 1;
    }

    // 0. fused prep (weights + trig) and res transpose
    prep_weights<<<2561, 256>>>(inw, outw, ffw1, ffw2);
    transpose_res<<<dim3(D_ / 32, T_ / 32, B_), 256>>>(res);
    // 1. FFT + top-k
    fft_topk<<<B_ * D_, 256>>>();
    // 2. season (rotation) + res1
    season_k<<<dim3(D_ / 256, TP_ / 16, B_), 256>>>(res, out_season);
    // 3. v = res1 @ in_w
    gemm_h<<<dim3(D_ / 128, (B_ * T_) / 128), 256, GSMEM>>>(
        B_ * T_, D_, D_, p_res1h, p_win, p_v, nullptr, 0, nullptr);
    // 4. growth EMA: finals, then rescan with carry -> half
    growth_fin<<<dim3(B_, GSEG), 512>>>(z0, gsw);
    growth_scan2<<<dim3(B_, GSEG), 512>>>(z0, gsw, gv0);
    // 5. growth = gpre @ out_w -> fp32 output
    gemm_h<<<dim3(D_ / 128, (B_ * T1_ + 127) / 128), 256, GSMEM>>>(
        B_ * T1_, D_, D_, p_gpre, p_wout, out_growth, nullptr, 0, nullptr);
    // 6. res2 = LN1(res1 - growth[:,1:])
    ln_kf<<<B_ * T_, 128>>>(p_res1f, out_growth, n1g, n1b, p_res2f, p_res2h);
    // 7. hid = gelu(res2 @ ff_w1) -> half
    gemm_h<<<dim3(LAT_ / 128, (B_ * T_) / 128), 256, GSMEM>>>(
        B_ * T_, LAT_, D_, p_res2h, p_wf1, nullptr, p_hid, 1, nullptr);
    // 8. pre = hid @ ff_w2 + res2
    gemm_h<<<dim3(D_ / 128, (B_ * T_) / 128), 256, GSMEM>>>(
        B_ * T_, D_, LAT_, p_hid, p_wf2, p_pre, nullptr, 2, p_res2f);
    // 9. res3 = LN2(pre)
    ln_kf<<<B_ * T_, 128>>>(p_pre, nullptr, n2g, n2b, out_res3, nullptr);
    // 10. skinny projections
    skinny2<<<dim3(B_ * T_, 2), 256>>>(out_growth, out_season, gpw, spw);
    // 11. level EMA segmented scan
    level_part<<<LSEG, 128>>>(lvl, lsw, out_level);
    level_apply<<<LSEG, 128>>>(lsw, lv0, out_level);
}